// round 14
// baseline (speedup 1.0000x reference)
#include <cuda_runtime.h>
#include <cuda_fp16.h>
#include <math_constants.h>
#include <cstdint>

// ---------------------------------------------------------------------------
// DIMES dense encoder, B=16, N=200, U=64, L=3
// w_l = w0(adj rank-1) + sum_i lrelu(bn_i(z_i)); z_i fp16.
// Edge kernels: 2x 64-row sub-tiles per block (E loaded once per block).
// F2 pre-projects w2 onto e1w (P2); k_last streams z2.
// ---------------------------------------------------------------------------

constexpr int B_ = 16, N_ = 200, M_ = 199, U_ = 64;
constexpr int BN_ = B_ * N_;                     // 3200
constexpr long long E_ = (long long)BN_ * M_;    // 636800
constexpr float EPS_ = 1e-5f;
constexpr int NSLOT = 16;

__device__ __align__(16) __half g_z16[3][(size_t)636800 * 64];
__device__ __align__(16) float g_P2[(size_t)636800];
__device__ __align__(16) float g_h[BN_ * U_];
__device__ __align__(16) float g_x1[BN_ * U_];
__device__ __align__(16) float g_x2[BN_ * U_];
__device__ __align__(16) float g_x3[BN_ * U_];
__device__ __align__(16) float g_x4[BN_ * U_];
__device__ unsigned g_pooled_u[BN_ * U_];
__device__ double g_estats[NSLOT][2][U_];        // per-slot stats
__device__ __align__(16) float g_ecoef[3][2][U_];
__device__ __align__(16) float g_hcoef[2 * U_];

__device__ __forceinline__ float lrelu(float v) { return v >= 0.f ? v : 0.01f * v; }

__device__ __forceinline__ unsigned enc_f(float f) {
    unsigned u = __float_as_uint(f);
    return u ^ ((u & 0x80000000u) ? 0xffffffffu : 0x80000000u);
}
__device__ __forceinline__ float dec_f(unsigned k) {
    return __uint_as_float((k & 0x80000000u) ? (k ^ 0x80000000u) : ~k);
}

__device__ __forceinline__ unsigned to_tf32(float f) {
    unsigned r;
    asm("cvt.rna.tf32.f32 %0, %1;" : "=r"(r) : "f"(f));
    return r;
}

__device__ __forceinline__ void mma_tf32(float c[4], unsigned a0, unsigned a1,
                                         unsigned a2, unsigned a3,
                                         unsigned b0, unsigned b1) {
    asm volatile(
        "mma.sync.aligned.m16n8k8.row.col.f32.tf32.tf32.f32 "
        "{%0,%1,%2,%3}, {%4,%5,%6,%7}, {%8,%9}, {%0,%1,%2,%3};"
        : "+f"(c[0]), "+f"(c[1]), "+f"(c[2]), "+f"(c[3])
        : "r"(a0), "r"(a1), "r"(a2), "r"(a3), "r"(b0), "r"(b1));
}

// C(64x64) = W(fp32 smem stride 68, cvt on load) @ E(tf32 smem [k][u] stride 72)
__device__ __forceinline__ void do_gemm(const float* __restrict__ W,
                                        const float* __restrict__ Em,
                                        float cf[4][4], int la, int ncol0, int tig) {
    const int grp = (threadIdx.x & 31) >> 2;
#pragma unroll
    for (int nt = 0; nt < 4; nt++) { cf[nt][0]=0.f; cf[nt][1]=0.f; cf[nt][2]=0.f; cf[nt][3]=0.f; }
#pragma unroll
    for (int k0 = 0; k0 < 64; k0 += 8) {
        unsigned a0 = to_tf32(W[la * 68 + k0 + tig]);
        unsigned a1 = to_tf32(W[(la + 8) * 68 + k0 + tig]);
        unsigned a2 = to_tf32(W[la * 68 + k0 + tig + 4]);
        unsigned a3 = to_tf32(W[(la + 8) * 68 + k0 + tig + 4]);
#pragma unroll
        for (int nt = 0; nt < 4; nt++) {
            int col = ncol0 + nt * 8 + grp;
            unsigned b0 = __float_as_uint(Em[(k0 + tig) * 72 + col]);
            unsigned b1 = __float_as_uint(Em[(k0 + tig + 4) * 72 + col]);
            mma_tf32(cf[nt], a0, a1, a2, a3, b0, b1);
        }
    }
}

// ---------------------------------------------------------------------------
// Edge kernel: grid = BN_*2, one block per (bn, 128-row macro-tile),
// two 64-row sub-tiles per block. 256 threads.
// ---------------------------------------------------------------------------
template<int NZ, bool POOLED, bool PROJ>
__global__ void __launch_bounds__(256) k_edge(
    const float* __restrict__ adj, const float* __restrict__ ew0, const float* __restrict__ eb0,
    const float* __restrict__ Ew,  const float* __restrict__ Eb,
    const float* __restrict__ e1w)
{
    __shared__ float W_sh[64 * 68];   // A tile; reused as z staging post-GEMM
    __shared__ float e_sh[64 * 72];   // E, persistent across sub-tiles
    __shared__ float zc_sh[64];
    __shared__ float ssum[64], ssq[64];
    __shared__ unsigned pool_sh[64];
    __shared__ float adj_sh[128];

    const int bid = blockIdx.x;
    const int bn = bid >> 1, half = bid & 1;
    const int mbase = half * 128;
    const int n = bn % N_, b = bn / N_;
    const int t = threadIdx.x;
    const int c = t & 15, r = t >> 4, c4 = c * 4;
    const int lane = t & 31, wp = t >> 5, grp = lane >> 2, tig = lane & 3;
    const int la = (wp & 3) * 16 + grp;
    const int lb = la + 8;
    const int ncol0 = (wp >> 2) * 32;
    const int slot = bid & (NSLOT - 1);

    if (t < 64) {
        zc_sh[t] = __ldg(&Eb[t]) + g_x3[bn * U_ + t];
        ssum[t] = 0.f; ssq[t] = 0.f;
        if (POOLED) pool_sh[t] = 0u;
    }
    if (t < 128) {
        int m = mbase + t;
        int dst = m + (m >= n);
        adj_sh[t] = (m < M_) ? __ldg(&adj[(size_t)bn * N_ + dst]) : 0.f;
    }
    for (int idx = t; idx < 1024; idx += 256) {
        int k = idx >> 4, q = (idx & 15) * 4;
        float4 v = __ldg((const float4*)&Ew[k * 64 + q]);
        v.x = __uint_as_float(to_tf32(v.x)); v.y = __uint_as_float(to_tf32(v.y));
        v.z = __uint_as_float(to_tf32(v.z)); v.w = __uint_as_float(to_tf32(v.w));
        *(float4*)&e_sh[k * 72 + q] = v;
    }
    __syncthreads();

    const float* x2b = &g_x2[(size_t)b * N_ * U_];
    const float* x4b = &g_x4[(size_t)b * N_ * U_];
    float4 ew04 = __ldg((const float4*)&ew0[c4]);
    float4 eb04 = __ldg((const float4*)&eb0[c4]);
    float4 e1;
    if (PROJ) e1 = __ldg((const float4*)&e1w[c4]);

    // accumulators across sub-tiles
    float4 pool4 = make_float4(-CUDART_INF_F, -CUDART_INF_F, -CUDART_INF_F, -CUDART_INF_F);
    float4 esum = make_float4(0.f, 0.f, 0.f, 0.f);
    float4 esq  = make_float4(0.f, 0.f, 0.f, 0.f);
    float4 zc4 = *(const float4*)&zc_sh[c4];

#pragma unroll 1
    for (int st = 0; st < 2; st++) {
        const int m0 = mbase + st * 64;

        // build w0 in registers
        float4 w4[4];
#pragma unroll
        for (int j = 0; j < 4; j++) {
            float a = adj_sh[st * 64 + 4 * r + j];
            w4[j].x = lrelu(fmaf(a, ew04.x, eb04.x));
            w4[j].y = lrelu(fmaf(a, ew04.y, eb04.y));
            w4[j].z = lrelu(fmaf(a, ew04.z, eb04.z));
            w4[j].w = lrelu(fmaf(a, ew04.w, eb04.w));
        }

        // apply previous layers' residuals from fp16 z
#pragma unroll
        for (int i = 0; i < NZ; i++) {
            float4 s4 = *(const float4*)&g_ecoef[i][0][c4];
            float4 f4 = *(const float4*)&g_ecoef[i][1][c4];
            const __half* zb = g_z16[i] + (size_t)bn * M_ * U_;
#pragma unroll
            for (int j = 0; j < 4; j++) {
                int m = m0 + 4 * r + j;
                if (m < M_) {
                    uint2 zr = *(const uint2*)&zb[(size_t)m * U_ + c4];
                    float2 za = __half22float2(*(__half2*)&zr.x);
                    float2 zz = __half22float2(*(__half2*)&zr.y);
                    w4[j].x += lrelu(fmaf(za.x, s4.x, f4.x));
                    w4[j].y += lrelu(fmaf(za.y, s4.y, f4.y));
                    w4[j].z += lrelu(fmaf(zz.x, s4.z, f4.z));
                    w4[j].w += lrelu(fmaf(zz.y, s4.w, f4.w));
                }
            }
        }

        if (PROJ) {
            float pj[4];
#pragma unroll
            for (int j = 0; j < 4; j++)
                pj[j] = w4[j].x * e1.x + w4[j].y * e1.y + w4[j].z * e1.z + w4[j].w * e1.w;
#pragma unroll
            for (int off = 1; off <= 8; off <<= 1) {
#pragma unroll
                for (int j = 0; j < 4; j++)
                    pj[j] += __shfl_xor_sync(0xffffffffu, pj[j], off);
            }
            if (c == 0) {
#pragma unroll
                for (int j = 0; j < 4; j++) {
                    int m = m0 + 4 * r + j;
                    if (m < M_) g_P2[(size_t)bn * M_ + m] = pj[j];
                }
            }
        }

        // pooled: register w, coalesced x2 loads
        if (POOLED) {
#pragma unroll
            for (int j = 0; j < 4; j++) {
                int m = m0 + 4 * r + j;
                if (m < M_) {
                    int dst = m + (m >= n);
                    float4 x2v = __ldg((const float4*)&x2b[dst * U_ + c4]);
                    pool4.x = fmaxf(pool4.x, x2v.x / (1.f + __expf(-w4[j].x)));
                    pool4.y = fmaxf(pool4.y, x2v.y / (1.f + __expf(-w4[j].y)));
                    pool4.z = fmaxf(pool4.z, x2v.z / (1.f + __expf(-w4[j].z)));
                    pool4.w = fmaxf(pool4.w, x2v.w / (1.f + __expf(-w4[j].w)));
                }
            }
        }

        // stash w to smem for GEMM A-fragments
#pragma unroll
        for (int j = 0; j < 4; j++)
            *(float4*)&W_sh[(4 * r + j) * 68 + c4] = w4[j];
        __syncthreads();

        float cf[4][4];
        do_gemm(W_sh, e_sh, cf, la, ncol0, tig);
        __syncthreads();   // all GEMM reads of W_sh done

        // stage z fragments into W_sh (dead post-GEMM), stride 68
#pragma unroll
        for (int nt = 0; nt < 4; nt++) {
            int cc = ncol0 + nt * 8 + 2 * tig;
            *(float2*)&W_sh[la * 68 + cc] = make_float2(cf[nt][0], cf[nt][1]);
            *(float2*)&W_sh[lb * 68 + cc] = make_float2(cf[nt][2], cf[nt][3]);
        }
        __syncthreads();

        // coalesced epilogue in (r,c) mapping
        __half* zo = g_z16[NZ] + (size_t)bn * M_ * U_;
#pragma unroll
        for (int j = 0; j < 4; j++) {
            int rr = 4 * r + j, m = m0 + rr;
            if (m < M_) {
                int dst = m + (m >= n);
                float4 z4 = *(const float4*)&W_sh[rr * 68 + c4];
                float4 x4v = __ldg((const float4*)&x4b[dst * U_ + c4]);
                z4.x += zc4.x + x4v.x;
                z4.y += zc4.y + x4v.y;
                z4.z += zc4.z + x4v.z;
                z4.w += zc4.w + x4v.w;
                uint2 zp;
                *(__half2*)&zp.x = __floats2half2_rn(z4.x, z4.y);
                *(__half2*)&zp.y = __floats2half2_rn(z4.z, z4.w);
                *(uint2*)&zo[(size_t)m * U_ + c4] = zp;
                esum.x += z4.x; esq.x = fmaf(z4.x, z4.x, esq.x);
                esum.y += z4.y; esq.y = fmaf(z4.y, z4.y, esq.y);
                esum.z += z4.z; esq.z = fmaf(z4.z, z4.z, esq.z);
                esum.w += z4.w; esq.w = fmaf(z4.w, z4.w, esq.w);
            }
        }
        __syncthreads();   // W_sh reuse guard for next sub-tile
    }

    // reduce over the two r-values per warp, then smem atomics
    esum.x += __shfl_xor_sync(0xffffffffu, esum.x, 16);
    esum.y += __shfl_xor_sync(0xffffffffu, esum.y, 16);
    esum.z += __shfl_xor_sync(0xffffffffu, esum.z, 16);
    esum.w += __shfl_xor_sync(0xffffffffu, esum.w, 16);
    esq.x  += __shfl_xor_sync(0xffffffffu, esq.x, 16);
    esq.y  += __shfl_xor_sync(0xffffffffu, esq.y, 16);
    esq.z  += __shfl_xor_sync(0xffffffffu, esq.z, 16);
    esq.w  += __shfl_xor_sync(0xffffffffu, esq.w, 16);
    if (POOLED) {
        pool4.x = fmaxf(pool4.x, __shfl_xor_sync(0xffffffffu, pool4.x, 16));
        pool4.y = fmaxf(pool4.y, __shfl_xor_sync(0xffffffffu, pool4.y, 16));
        pool4.z = fmaxf(pool4.z, __shfl_xor_sync(0xffffffffu, pool4.z, 16));
        pool4.w = fmaxf(pool4.w, __shfl_xor_sync(0xffffffffu, pool4.w, 16));
    }
    if (lane < 16) {
        atomicAdd(&ssum[c4 + 0], esum.x); atomicAdd(&ssum[c4 + 1], esum.y);
        atomicAdd(&ssum[c4 + 2], esum.z); atomicAdd(&ssum[c4 + 3], esum.w);
        atomicAdd(&ssq[c4 + 0], esq.x);   atomicAdd(&ssq[c4 + 1], esq.y);
        atomicAdd(&ssq[c4 + 2], esq.z);   atomicAdd(&ssq[c4 + 3], esq.w);
        if (POOLED) {
            atomicMax(&pool_sh[c4 + 0], enc_f(pool4.x));
            atomicMax(&pool_sh[c4 + 1], enc_f(pool4.y));
            atomicMax(&pool_sh[c4 + 2], enc_f(pool4.z));
            atomicMax(&pool_sh[c4 + 3], enc_f(pool4.w));
        }
    }
    __syncthreads();
    if (t < 64) {
        atomicAdd(&g_estats[slot][0][t], (double)ssum[t]);
        atomicAdd(&g_estats[slot][1][t], (double)ssq[t]);
        if (POOLED) atomicMax(&g_pooled_u[bn * U_ + t], pool_sh[t]);
    }
}

// final: out = P2 + dot(lrelu(bn2(z2)), e1w) + e1b. Dense tile blocks.
__global__ void __launch_bounds__(256) k_last(const float* __restrict__ e1w,
                                              const float* __restrict__ e1b,
                                              float* __restrict__ out) {
    const int bid = blockIdx.x;
    const int bn = bid >> 2, tile = bid & 3;
    const int m0 = tile * 64;
    const int n = bn % N_;
    const int t = threadIdx.x;
    const int c = t & 15, r = t >> 4, c4 = c * 4;

    if (tile == 0 && t == 0) out[(size_t)bn * N_ + n] = 0.f;

    float4 e1 = __ldg((const float4*)&e1w[c4]);
    float4 s4 = *(const float4*)&g_ecoef[2][0][c4];
    float4 f4 = *(const float4*)&g_ecoef[2][1][c4];
    const __half* zb = g_z16[2] + (size_t)bn * M_ * U_;

    float pj[4];
#pragma unroll
    for (int j = 0; j < 4; j++) {
        int m = m0 + 4 * r + j;
        pj[j] = 0.f;
        if (m < M_) {
            uint2 zr = *(const uint2*)&zb[(size_t)m * U_ + c4];
            float2 za = __half22float2(*(__half2*)&zr.x);
            float2 zz = __half22float2(*(__half2*)&zr.y);
            float a0 = lrelu(fmaf(za.x, s4.x, f4.x));
            float a1 = lrelu(fmaf(za.y, s4.y, f4.y));
            float a2 = lrelu(fmaf(zz.x, s4.z, f4.z));
            float a3 = lrelu(fmaf(zz.y, s4.w, f4.w));
            pj[j] = a0 * e1.x + a1 * e1.y + a2 * e1.z + a3 * e1.w;
        }
    }
#pragma unroll
    for (int off = 1; off <= 8; off <<= 1) {
#pragma unroll
        for (int j = 0; j < 4; j++)
            pj[j] += __shfl_xor_sync(0xffffffffu, pj[j], off);
    }
    if (c == 0) {
        float bias = __ldg(&e1b[0]);
#pragma unroll
        for (int j = 0; j < 4; j++) {
            int m = m0 + 4 * r + j;
            if (m < M_) {
                int dst = m + (m >= n);
                out[(size_t)bn * N_ + dst] =
                    pj[j] + g_P2[(size_t)bn * M_ + m] + bias;
            }
        }
    }
}

// node path: h init/update + x1..x4 GEMVs. One block per bn.
__global__ void __launch_bounds__(256) k_node(
    const float* __restrict__ x, const float* __restrict__ l0w, const float* __restrict__ l0b,
    int first,
    const float* __restrict__ w1, const float* __restrict__ b1,
    const float* __restrict__ w2, const float* __restrict__ b2,
    const float* __restrict__ w3, const float* __restrict__ b3,
    const float* __restrict__ w4, const float* __restrict__ b4)
{
    __shared__ float hsh[U_];
    int bn = blockIdx.x, t = threadIdx.x;
    if (t < U_) {
        float hv;
        if (first) {
            hv = lrelu(x[bn * 2] * __ldg(&l0w[t]) + x[bn * 2 + 1] * __ldg(&l0w[U_ + t]) + __ldg(&l0b[t]));
        } else {
            float zh = g_x1[bn * U_ + t] + dec_f(g_pooled_u[bn * U_ + t]);
            hv = g_h[bn * U_ + t] + lrelu(fmaf(zh, g_hcoef[t], g_hcoef[U_ + t]));
        }
        hsh[t] = hv;
        g_h[bn * U_ + t] = hv;
        g_pooled_u[bn * U_ + t] = 0u;   // reset for this layer's pooling
    }
    __syncthreads();
    int mat = t >> 6, col = t & 63;
    const float* W; const float* bb; float* xout;
    switch (mat) {
        case 0:  W = w1; bb = b1; xout = g_x1; break;
        case 1:  W = w2; bb = b2; xout = g_x2; break;
        case 2:  W = w3; bb = b3; xout = g_x3; break;
        default: W = w4; bb = b4; xout = g_x4; break;
    }
    float acc = __ldg(&bb[col]);
#pragma unroll
    for (int k = 0; k < U_; k++) acc = fmaf(hsh[k], __ldg(&W[k * U_ + col]), acc);
    xout[bn * U_ + col] = acc;
}

// fused h-stats + finalize for layer l: 64 blocks (one per u).
__global__ void __launch_bounds__(256) k_hfin(int l,
        const float* __restrict__ hg, const float* __restrict__ hb,
        const float* __restrict__ eg, const float* __restrict__ eb) {
    __shared__ float rs[256], rq[256];
    int u = blockIdx.x, t = threadIdx.x;
    float s = 0.f, q = 0.f;
    for (int i = t; i < BN_; i += 256) {
        float v = g_x1[i * U_ + u] + dec_f(g_pooled_u[i * U_ + u]);
        s += v; q = fmaf(v, v, q);
    }
    rs[t] = s; rq[t] = q;
    __syncthreads();
    for (int off = 128; off >= 1; off >>= 1) {
        if (t < off) { rs[t] += rs[t + off]; rq[t] += rq[t + off]; }
        __syncthreads();
    }
    if (t == 0) {
        float hmean = rs[0] / (float)BN_;
        float hvar  = rq[0] / (float)BN_ - hmean * hmean;
        float hs = __ldg(&hg[u]) * rsqrtf(hvar + EPS_);
        g_hcoef[u] = hs;
        g_hcoef[U_ + u] = __ldg(&hb[u]) - hmean * hs;

        double es = 0.0, eq2 = 0.0;
#pragma unroll
        for (int sl = 0; sl < NSLOT; sl++) {
            es += g_estats[sl][0][u]; eq2 += g_estats[sl][1][u];
            g_estats[sl][0][u] = 0.0; g_estats[sl][1][u] = 0.0;
        }
        float emean = (float)(es / (double)E_);
        float evar  = (float)(eq2 / (double)E_) - emean * emean;
        float esc = __ldg(&eg[u]) * rsqrtf(evar + EPS_);
        g_ecoef[l][0][u] = esc;
        g_ecoef[l][1][u] = __ldg(&eb[u]) - emean * esc;
    }
}

// layer-2 finalize (ecoef only)
__global__ void k_fin2(const float* __restrict__ eg, const float* __restrict__ eb) {
    int u = threadIdx.x;  // 64
    double es = 0.0, eq = 0.0;
#pragma unroll
    for (int sl = 0; sl < NSLOT; sl++) {
        es += g_estats[sl][0][u]; eq += g_estats[sl][1][u];
        g_estats[sl][0][u] = 0.0; g_estats[sl][1][u] = 0.0;
    }
    float emean = (float)(es / (double)E_);
    float evar  = (float)(eq / (double)E_) - emean * emean;
    float esc = eg[u] * rsqrtf(evar + EPS_);
    g_ecoef[2][0][u] = esc;
    g_ecoef[2][1][u] = eb[u] - emean * esc;
}

extern "C" void kernel_launch(void* const* d_in, const int* in_sizes, int n_in,
                              void* d_out, int out_size) {
    const float* x    = (const float*)d_in[0];
    const float* adj  = (const float*)d_in[1];
    const float* vl0w = (const float*)d_in[2];
    const float* vl0b = (const float*)d_in[3];
    const float* vw1  = (const float*)d_in[4];
    const float* vb1  = (const float*)d_in[5];
    const float* vw2  = (const float*)d_in[6];
    const float* vb2  = (const float*)d_in[7];
    const float* vw3  = (const float*)d_in[8];
    const float* vb3  = (const float*)d_in[9];
    const float* vw4  = (const float*)d_in[10];
    const float* vb4  = (const float*)d_in[11];
    const float* vbng = (const float*)d_in[12];
    const float* vbnb = (const float*)d_in[13];
    const float* el0w = (const float*)d_in[14];
    const float* el0b = (const float*)d_in[15];
    const float* ew   = (const float*)d_in[16];
    const float* eb   = (const float*)d_in[17];
    const float* ebng = (const float*)d_in[18];
    const float* ebnb = (const float*)d_in[19];
    const float* e1w  = (const float*)d_in[20];
    const float* e1b  = (const float*)d_in[21];
    float* out = (float*)d_out;

    auto S0 = k_edge<0, true,  false>;
    auto F1 = k_edge<1, true,  false>;
    auto F2 = k_edge<2, false, true >;   // + P2 projection
    const int G2 = BN_ * 2;

    // layer 0
    k_node<<<BN_, 256>>>(x, vl0w, vl0b, 1,
                         vw1, vb1, vw2, vb2, vw3, vb3, vw4, vb4);
    S0<<<G2, 256>>>(adj, el0w, el0b, ew, eb, nullptr);
    k_hfin<<<64, 256>>>(0, vbng, vbnb, ebng, ebnb);

    // layer 1
    k_node<<<BN_, 256>>>(x, vl0w, vl0b, 0,
                         vw1 + 4096, vb1 + 64, vw2 + 4096, vb2 + 64,
                         vw3 + 4096, vb3 + 64, vw4 + 4096, vb4 + 64);
    F1<<<G2, 256>>>(adj, el0w, el0b, ew + 4096, eb + 64, nullptr);
    k_hfin<<<64, 256>>>(1, vbng + 64, vbnb + 64, ebng + 64, ebnb + 64);

    // layer 2
    k_node<<<BN_, 256>>>(x, vl0w, vl0b, 0,
                         vw1 + 8192, vb1 + 128, vw2 + 8192, vb2 + 128,
                         vw3 + 8192, vb3 + 128, vw4 + 8192, vb4 + 128);
    F2<<<G2, 256>>>(adj, el0w, el0b, ew + 8192, eb + 128, e1w);
    k_fin2<<<1, 64>>>(ebng + 128, ebnb + 128);

    // final: stream z2 + P2 -> out (diag zeroed inside)
    k_last<<<BN_ * 4, 256>>>(e1w, e1b, out);
}

// round 15
// speedup vs baseline: 1.1590x; 1.1590x over previous
#include <cuda_runtime.h>
#include <cuda_fp16.h>
#include <math_constants.h>
#include <cstdint>

// ---------------------------------------------------------------------------
// DIMES dense encoder, B=16, N=200, U=64, L=3   (R13 structure + 16 stat slots)
// w_l = w0(adj rank-1) + sum_i lrelu(bn_i(z_i)); z_i fp16.
// F2 pre-projects w2 onto e1w (P2); k_last streams z2 in dense tile blocks.
// ---------------------------------------------------------------------------

constexpr int B_ = 16, N_ = 200, M_ = 199, U_ = 64;
constexpr int BN_ = B_ * N_;                     // 3200
constexpr long long E_ = (long long)BN_ * M_;    // 636800
constexpr float EPS_ = 1e-5f;
constexpr int NSLOT = 16;

__device__ __align__(16) __half g_z16[3][(size_t)636800 * 64];
__device__ __align__(16) float g_P2[(size_t)636800];
__device__ __align__(16) float g_h[BN_ * U_];
__device__ __align__(16) float g_x1[BN_ * U_];
__device__ __align__(16) float g_x2[BN_ * U_];
__device__ __align__(16) float g_x3[BN_ * U_];
__device__ __align__(16) float g_x4[BN_ * U_];
__device__ unsigned g_pooled_u[BN_ * U_];
__device__ double g_estats[NSLOT][2][U_];        // per-slot stats
__device__ __align__(16) float g_ecoef[3][2][U_];
__device__ __align__(16) float g_hcoef[2 * U_];

__device__ __forceinline__ float lrelu(float v) { return v >= 0.f ? v : 0.01f * v; }

__device__ __forceinline__ unsigned enc_f(float f) {
    unsigned u = __float_as_uint(f);
    return u ^ ((u & 0x80000000u) ? 0xffffffffu : 0x80000000u);
}
__device__ __forceinline__ float dec_f(unsigned k) {
    return __uint_as_float((k & 0x80000000u) ? (k ^ 0x80000000u) : ~k);
}

__device__ __forceinline__ unsigned to_tf32(float f) {
    unsigned r;
    asm("cvt.rna.tf32.f32 %0, %1;" : "=r"(r) : "f"(f));
    return r;
}

__device__ __forceinline__ void mma_tf32(float c[4], unsigned a0, unsigned a1,
                                         unsigned a2, unsigned a3,
                                         unsigned b0, unsigned b1) {
    asm volatile(
        "mma.sync.aligned.m16n8k8.row.col.f32.tf32.tf32.f32 "
        "{%0,%1,%2,%3}, {%4,%5,%6,%7}, {%8,%9}, {%0,%1,%2,%3};"
        : "+f"(c[0]), "+f"(c[1]), "+f"(c[2]), "+f"(c[3])
        : "r"(a0), "r"(a1), "r"(a2), "r"(a3), "r"(b0), "r"(b1));
}

// C(64x64) = W(fp32 smem stride 68, cvt on load) @ E(tf32 smem [k][u] stride 72)
__device__ __forceinline__ void do_gemm(const float* __restrict__ W,
                                        const float* __restrict__ Em,
                                        float cf[4][4], int la, int ncol0, int tig) {
    const int grp = (threadIdx.x & 31) >> 2;
#pragma unroll
    for (int nt = 0; nt < 4; nt++) { cf[nt][0]=0.f; cf[nt][1]=0.f; cf[nt][2]=0.f; cf[nt][3]=0.f; }
#pragma unroll
    for (int k0 = 0; k0 < 64; k0 += 8) {
        unsigned a0 = to_tf32(W[la * 68 + k0 + tig]);
        unsigned a1 = to_tf32(W[(la + 8) * 68 + k0 + tig]);
        unsigned a2 = to_tf32(W[la * 68 + k0 + tig + 4]);
        unsigned a3 = to_tf32(W[(la + 8) * 68 + k0 + tig + 4]);
#pragma unroll
        for (int nt = 0; nt < 4; nt++) {
            int col = ncol0 + nt * 8 + grp;
            unsigned b0 = __float_as_uint(Em[(k0 + tig) * 72 + col]);
            unsigned b1 = __float_as_uint(Em[(k0 + tig + 4) * 72 + col]);
            mma_tf32(cf[nt], a0, a1, a2, a3, b0, b1);
        }
    }
}

// ---------------------------------------------------------------------------
// Edge kernel: grid = BN_*4, one block per (bn, 64-row tile), 256 threads.
// Build w0 from adj in regs; apply NZ residuals from fp16 z (coalesced);
// optional PROJ: write P2 = dot(w, e1w) per row; then GEMM + stats (+POOLED).
// ---------------------------------------------------------------------------
template<int NZ, bool POOLED, bool PROJ>
__global__ void __launch_bounds__(256) k_edge(
    const float* __restrict__ adj, const float* __restrict__ ew0, const float* __restrict__ eb0,
    const float* __restrict__ Ew,  const float* __restrict__ Eb,
    const float* __restrict__ e1w)
{
    __shared__ float W_sh[64 * 68];
    __shared__ float e_sh[64 * 72];   // E for GEMM; reused as z staging
    __shared__ float zc_sh[64];
    __shared__ float ssum[64], ssq[64];
    __shared__ unsigned pool_sh[64];
    __shared__ float adj_sh[64];

    const int bid = blockIdx.x;
    const int bn = bid >> 2, tile = bid & 3;
    const int m0 = tile * 64;
    const int n = bn % N_, b = bn / N_;
    const int t = threadIdx.x;
    const int c = t & 15, r = t >> 4, c4 = c * 4;
    const int lane = t & 31, wp = t >> 5, grp = lane >> 2, tig = lane & 3;
    const int la = (wp & 3) * 16 + grp;
    const int lb = la + 8;
    const int ncol0 = (wp >> 2) * 32;
    const int slot = bid & (NSLOT - 1);

    if (t < 64) {
        int m = m0 + t;
        int dst = m + (m >= n);
        adj_sh[t] = (m < M_) ? __ldg(&adj[(size_t)bn * N_ + dst]) : 0.f;
        zc_sh[t] = __ldg(&Eb[t]) + g_x3[bn * U_ + t];
        ssum[t] = 0.f; ssq[t] = 0.f;
        if (POOLED) pool_sh[t] = 0u;
    }
    for (int idx = t; idx < 1024; idx += 256) {
        int k = idx >> 4, q = (idx & 15) * 4;
        float4 v = __ldg((const float4*)&Ew[k * 64 + q]);
        v.x = __uint_as_float(to_tf32(v.x)); v.y = __uint_as_float(to_tf32(v.y));
        v.z = __uint_as_float(to_tf32(v.z)); v.w = __uint_as_float(to_tf32(v.w));
        *(float4*)&e_sh[k * 72 + q] = v;
    }
    __syncthreads();

    // --- build w0 in registers (rows 4r+j, cols c4..c4+3) ---
    float4 ew04 = __ldg((const float4*)&ew0[c4]);
    float4 eb04 = __ldg((const float4*)&eb0[c4]);
    float4 w4[4];
#pragma unroll
    for (int j = 0; j < 4; j++) {
        float a = adj_sh[4 * r + j];
        w4[j].x = lrelu(fmaf(a, ew04.x, eb04.x));
        w4[j].y = lrelu(fmaf(a, ew04.y, eb04.y));
        w4[j].z = lrelu(fmaf(a, ew04.z, eb04.z));
        w4[j].w = lrelu(fmaf(a, ew04.w, eb04.w));
    }

    // --- apply previous layers' residuals from fp16 z (coalesced loads) ---
#pragma unroll
    for (int i = 0; i < NZ; i++) {
        float4 s4 = *(const float4*)&g_ecoef[i][0][c4];
        float4 f4 = *(const float4*)&g_ecoef[i][1][c4];
        const __half* zb = g_z16[i] + (size_t)bn * M_ * U_;
#pragma unroll
        for (int j = 0; j < 4; j++) {
            int m = m0 + 4 * r + j;
            if (m < M_) {
                uint2 zr = *(const uint2*)&zb[(size_t)m * U_ + c4];
                float2 za = __half22float2(*(__half2*)&zr.x);
                float2 zz = __half22float2(*(__half2*)&zr.y);
                w4[j].x += lrelu(fmaf(za.x, s4.x, f4.x));
                w4[j].y += lrelu(fmaf(za.y, s4.y, f4.y));
                w4[j].z += lrelu(fmaf(zz.x, s4.z, f4.z));
                w4[j].w += lrelu(fmaf(zz.y, s4.w, f4.w));
            }
        }
    }

    if (PROJ) {
        // partial projection of current w onto e1w -> g_P2 (no bias)
        float4 e1 = __ldg((const float4*)&e1w[c4]);
        float pj[4];
#pragma unroll
        for (int j = 0; j < 4; j++)
            pj[j] = w4[j].x * e1.x + w4[j].y * e1.y + w4[j].z * e1.z + w4[j].w * e1.w;
#pragma unroll
        for (int off = 1; off <= 8; off <<= 1) {
#pragma unroll
            for (int j = 0; j < 4; j++)
                pj[j] += __shfl_xor_sync(0xffffffffu, pj[j], off);
        }
        if (c == 0) {
#pragma unroll
            for (int j = 0; j < 4; j++) {
                int m = m0 + 4 * r + j;
                if (m < M_) g_P2[(size_t)bn * M_ + m] = pj[j];
            }
        }
    }

    const float* x2b = &g_x2[(size_t)b * N_ * U_];
    const float* x4b = &g_x4[(size_t)b * N_ * U_];

    // pooled pre-GEMM: register w, coalesced x2 row loads
    float4 pool4 = make_float4(-CUDART_INF_F, -CUDART_INF_F, -CUDART_INF_F, -CUDART_INF_F);
    if (POOLED) {
#pragma unroll
        for (int j = 0; j < 4; j++) {
            int m = m0 + 4 * r + j;
            if (m < M_) {
                int dst = m + (m >= n);
                float4 x2v = __ldg((const float4*)&x2b[dst * U_ + c4]);
                pool4.x = fmaxf(pool4.x, x2v.x / (1.f + __expf(-w4[j].x)));
                pool4.y = fmaxf(pool4.y, x2v.y / (1.f + __expf(-w4[j].y)));
                pool4.z = fmaxf(pool4.z, x2v.z / (1.f + __expf(-w4[j].z)));
                pool4.w = fmaxf(pool4.w, x2v.w / (1.f + __expf(-w4[j].w)));
            }
        }
    }

    // stash w to smem for GEMM A-fragments
#pragma unroll
    for (int j = 0; j < 4; j++)
        *(float4*)&W_sh[(4 * r + j) * 68 + c4] = w4[j];
    __syncthreads();

    float cf[4][4];
    do_gemm(W_sh, e_sh, cf, la, ncol0, tig);
    __syncthreads();   // all GEMM reads of e_sh done

    // stage z fragments into e_sh (now dead), stride 68
#pragma unroll
    for (int nt = 0; nt < 4; nt++) {
        int cc = ncol0 + nt * 8 + 2 * tig;
        *(float2*)&e_sh[la * 68 + cc] = make_float2(cf[nt][0], cf[nt][1]);
        *(float2*)&e_sh[lb * 68 + cc] = make_float2(cf[nt][2], cf[nt][3]);
    }
    __syncthreads();

    // coalesced epilogue in (r,c) mapping
    __half* zo = g_z16[NZ] + (size_t)bn * M_ * U_;
    float4 zc4 = *(const float4*)&zc_sh[c4];
    float4 esum = make_float4(0.f, 0.f, 0.f, 0.f);
    float4 esq  = make_float4(0.f, 0.f, 0.f, 0.f);
#pragma unroll
    for (int j = 0; j < 4; j++) {
        int rr = 4 * r + j, m = m0 + rr;
        if (m < M_) {
            int dst = m + (m >= n);
            float4 z4 = *(const float4*)&e_sh[rr * 68 + c4];
            float4 x4v = __ldg((const float4*)&x4b[dst * U_ + c4]);
            z4.x += zc4.x + x4v.x;
            z4.y += zc4.y + x4v.y;
            z4.z += zc4.z + x4v.z;
            z4.w += zc4.w + x4v.w;
            uint2 zp;
            *(__half2*)&zp.x = __floats2half2_rn(z4.x, z4.y);
            *(__half2*)&zp.y = __floats2half2_rn(z4.z, z4.w);
            *(uint2*)&zo[(size_t)m * U_ + c4] = zp;
            esum.x += z4.x; esq.x = fmaf(z4.x, z4.x, esq.x);
            esum.y += z4.y; esq.y = fmaf(z4.y, z4.y, esq.y);
            esum.z += z4.z; esq.z = fmaf(z4.z, z4.z, esq.z);
            esum.w += z4.w; esq.w = fmaf(z4.w, z4.w, esq.w);
        }
    }

    // reduce over the two r-values per warp, then smem atomics
    esum.x += __shfl_xor_sync(0xffffffffu, esum.x, 16);
    esum.y += __shfl_xor_sync(0xffffffffu, esum.y, 16);
    esum.z += __shfl_xor_sync(0xffffffffu, esum.z, 16);
    esum.w += __shfl_xor_sync(0xffffffffu, esum.w, 16);
    esq.x  += __shfl_xor_sync(0xffffffffu, esq.x, 16);
    esq.y  += __shfl_xor_sync(0xffffffffu, esq.y, 16);
    esq.z  += __shfl_xor_sync(0xffffffffu, esq.z, 16);
    esq.w  += __shfl_xor_sync(0xffffffffu, esq.w, 16);
    if (POOLED) {
        pool4.x = fmaxf(pool4.x, __shfl_xor_sync(0xffffffffu, pool4.x, 16));
        pool4.y = fmaxf(pool4.y, __shfl_xor_sync(0xffffffffu, pool4.y, 16));
        pool4.z = fmaxf(pool4.z, __shfl_xor_sync(0xffffffffu, pool4.z, 16));
        pool4.w = fmaxf(pool4.w, __shfl_xor_sync(0xffffffffu, pool4.w, 16));
    }
    if (lane < 16) {
        atomicAdd(&ssum[c4 + 0], esum.x); atomicAdd(&ssum[c4 + 1], esum.y);
        atomicAdd(&ssum[c4 + 2], esum.z); atomicAdd(&ssum[c4 + 3], esum.w);
        atomicAdd(&ssq[c4 + 0], esq.x);   atomicAdd(&ssq[c4 + 1], esq.y);
        atomicAdd(&ssq[c4 + 2], esq.z);   atomicAdd(&ssq[c4 + 3], esq.w);
        if (POOLED) {
            atomicMax(&pool_sh[c4 + 0], enc_f(pool4.x));
            atomicMax(&pool_sh[c4 + 1], enc_f(pool4.y));
            atomicMax(&pool_sh[c4 + 2], enc_f(pool4.z));
            atomicMax(&pool_sh[c4 + 3], enc_f(pool4.w));
        }
    }
    __syncthreads();
    if (t < 64) {
        atomicAdd(&g_estats[slot][0][t], (double)ssum[t]);
        atomicAdd(&g_estats[slot][1][t], (double)ssq[t]);
        if (POOLED) atomicMax(&g_pooled_u[bn * U_ + t], pool_sh[t]);
    }
}

// final: out = P2 + dot(lrelu(bn2(z2)), e1w) + e1b.
// Dense tile blocks: grid = BN_*4. Diag zeroed by tile 0 thread 0.
__global__ void __launch_bounds__(256) k_last(const float* __restrict__ e1w,
                                              const float* __restrict__ e1b,
                                              float* __restrict__ out) {
    const int bid = blockIdx.x;
    const int bn = bid >> 2, tile = bid & 3;
    const int m0 = tile * 64;
    const int n = bn % N_;
    const int t = threadIdx.x;
    const int c = t & 15, r = t >> 4, c4 = c * 4;

    if (tile == 0 && t == 0) out[(size_t)bn * N_ + n] = 0.f;

    float4 e1 = __ldg((const float4*)&e1w[c4]);
    float4 s4 = *(const float4*)&g_ecoef[2][0][c4];
    float4 f4 = *(const float4*)&g_ecoef[2][1][c4];
    const __half* zb = g_z16[2] + (size_t)bn * M_ * U_;

    float pj[4];
#pragma unroll
    for (int j = 0; j < 4; j++) {
        int m = m0 + 4 * r + j;
        pj[j] = 0.f;
        if (m < M_) {
            uint2 zr = *(const uint2*)&zb[(size_t)m * U_ + c4];
            float2 za = __half22float2(*(__half2*)&zr.x);
            float2 zz = __half22float2(*(__half2*)&zr.y);
            float a0 = lrelu(fmaf(za.x, s4.x, f4.x));
            float a1 = lrelu(fmaf(za.y, s4.y, f4.y));
            float a2 = lrelu(fmaf(zz.x, s4.z, f4.z));
            float a3 = lrelu(fmaf(zz.y, s4.w, f4.w));
            pj[j] = a0 * e1.x + a1 * e1.y + a2 * e1.z + a3 * e1.w;
        }
    }
#pragma unroll
    for (int off = 1; off <= 8; off <<= 1) {
#pragma unroll
        for (int j = 0; j < 4; j++)
            pj[j] += __shfl_xor_sync(0xffffffffu, pj[j], off);
    }
    if (c == 0) {
        float bias = __ldg(&e1b[0]);
#pragma unroll
        for (int j = 0; j < 4; j++) {
            int m = m0 + 4 * r + j;
            if (m < M_) {
                int dst = m + (m >= n);
                out[(size_t)bn * N_ + dst] =
                    pj[j] + g_P2[(size_t)bn * M_ + m] + bias;
            }
        }
    }
}

// node path: h init/update + x1..x4 GEMVs. One block per bn.
__global__ void __launch_bounds__(256) k_node(
    const float* __restrict__ x, const float* __restrict__ l0w, const float* __restrict__ l0b,
    int first,
    const float* __restrict__ w1, const float* __restrict__ b1,
    const float* __restrict__ w2, const float* __restrict__ b2,
    const float* __restrict__ w3, const float* __restrict__ b3,
    const float* __restrict__ w4, const float* __restrict__ b4)
{
    __shared__ float hsh[U_];
    int bn = blockIdx.x, t = threadIdx.x;
    if (t < U_) {
        float hv;
        if (first) {
            hv = lrelu(x[bn * 2] * __ldg(&l0w[t]) + x[bn * 2 + 1] * __ldg(&l0w[U_ + t]) + __ldg(&l0b[t]));
        } else {
            float zh = g_x1[bn * U_ + t] + dec_f(g_pooled_u[bn * U_ + t]);
            hv = g_h[bn * U_ + t] + lrelu(fmaf(zh, g_hcoef[t], g_hcoef[U_ + t]));
        }
        hsh[t] = hv;
        g_h[bn * U_ + t] = hv;
        g_pooled_u[bn * U_ + t] = 0u;   // reset for this layer's pooling
    }
    __syncthreads();
    int mat = t >> 6, col = t & 63;
    const float* W; const float* bb; float* xout;
    switch (mat) {
        case 0:  W = w1; bb = b1; xout = g_x1; break;
        case 1:  W = w2; bb = b2; xout = g_x2; break;
        case 2:  W = w3; bb = b3; xout = g_x3; break;
        default: W = w4; bb = b4; xout = g_x4; break;
    }
    float acc = __ldg(&bb[col]);
#pragma unroll
    for (int k = 0; k < U_; k++) acc = fmaf(hsh[k], __ldg(&W[k * U_ + col]), acc);
    xout[bn * U_ + col] = acc;
}

// fused h-stats + finalize for layer l: 64 blocks (one per u).
__global__ void __launch_bounds__(256) k_hfin(int l,
        const float* __restrict__ hg, const float* __restrict__ hb,
        const float* __restrict__ eg, const float* __restrict__ eb) {
    __shared__ float rs[256], rq[256];
    int u = blockIdx.x, t = threadIdx.x;
    float s = 0.f, q = 0.f;
    for (int i = t; i < BN_; i += 256) {
        float v = g_x1[i * U_ + u] + dec_f(g_pooled_u[i * U_ + u]);
        s += v; q = fmaf(v, v, q);
    }
    rs[t] = s; rq[t] = q;
    __syncthreads();
    for (int off = 128; off >= 1; off >>= 1) {
        if (t < off) { rs[t] += rs[t + off]; rq[t] += rq[t + off]; }
        __syncthreads();
    }
    if (t == 0) {
        float hmean = rs[0] / (float)BN_;
        float hvar  = rq[0] / (float)BN_ - hmean * hmean;
        float hs = __ldg(&hg[u]) * rsqrtf(hvar + EPS_);
        g_hcoef[u] = hs;
        g_hcoef[U_ + u] = __ldg(&hb[u]) - hmean * hs;

        double es = 0.0, eq2 = 0.0;
#pragma unroll
        for (int sl = 0; sl < NSLOT; sl++) {
            es += g_estats[sl][0][u]; eq2 += g_estats[sl][1][u];
            g_estats[sl][0][u] = 0.0; g_estats[sl][1][u] = 0.0;
        }
        float emean = (float)(es / (double)E_);
        float evar  = (float)(eq2 / (double)E_) - emean * emean;
        float esc = __ldg(&eg[u]) * rsqrtf(evar + EPS_);
        g_ecoef[l][0][u] = esc;
        g_ecoef[l][1][u] = __ldg(&eb[u]) - emean * esc;
    }
}

// layer-2 finalize (ecoef only)
__global__ void k_fin2(const float* __restrict__ eg, const float* __restrict__ eb) {
    int u = threadIdx.x;  // 64
    double es = 0.0, eq = 0.0;
#pragma unroll
    for (int sl = 0; sl < NSLOT; sl++) {
        es += g_estats[sl][0][u]; eq += g_estats[sl][1][u];
        g_estats[sl][0][u] = 0.0; g_estats[sl][1][u] = 0.0;
    }
    float emean = (float)(es / (double)E_);
    float evar  = (float)(eq / (double)E_) - emean * emean;
    float esc = eg[u] * rsqrtf(evar + EPS_);
    g_ecoef[2][0][u] = esc;
    g_ecoef[2][1][u] = eb[u] - emean * esc;
}

extern "C" void kernel_launch(void* const* d_in, const int* in_sizes, int n_in,
                              void* d_out, int out_size) {
    const float* x    = (const float*)d_in[0];
    const float* adj  = (const float*)d_in[1];
    const float* vl0w = (const float*)d_in[2];
    const float* vl0b = (const float*)d_in[3];
    const float* vw1  = (const float*)d_in[4];
    const float* vb1  = (const float*)d_in[5];
    const float* vw2  = (const float*)d_in[6];
    const float* vb2  = (const float*)d_in[7];
    const float* vw3  = (const float*)d_in[8];
    const float* vb3  = (const float*)d_in[9];
    const float* vw4  = (const float*)d_in[10];
    const float* vb4  = (const float*)d_in[11];
    const float* vbng = (const float*)d_in[12];
    const float* vbnb = (const float*)d_in[13];
    const float* el0w = (const float*)d_in[14];
    const float* el0b = (const float*)d_in[15];
    const float* ew   = (const float*)d_in[16];
    const float* eb   = (const float*)d_in[17];
    const float* ebng = (const float*)d_in[18];
    const float* ebnb = (const float*)d_in[19];
    const float* e1w  = (const float*)d_in[20];
    const float* e1b  = (const float*)d_in[21];
    float* out = (float*)d_out;

    auto S0 = k_edge<0, true,  false>;
    auto F1 = k_edge<1, true,  false>;
    auto F2 = k_edge<2, false, true >;   // + P2 projection
    const int G = BN_ * 4;

    // layer 0
    k_node<<<BN_, 256>>>(x, vl0w, vl0b, 1,
                         vw1, vb1, vw2, vb2, vw3, vb3, vw4, vb4);
    S0<<<G, 256>>>(adj, el0w, el0b, ew, eb, nullptr);
    k_hfin<<<64, 256>>>(0, vbng, vbnb, ebng, ebnb);

    // layer 1
    k_node<<<BN_, 256>>>(x, vl0w, vl0b, 0,
                         vw1 + 4096, vb1 + 64, vw2 + 4096, vb2 + 64,
                         vw3 + 4096, vb3 + 64, vw4 + 4096, vb4 + 64);
    F1<<<G, 256>>>(adj, el0w, el0b, ew + 4096, eb + 64, nullptr);
    k_hfin<<<64, 256>>>(1, vbng + 64, vbnb + 64, ebng + 64, ebnb + 64);

    // layer 2
    k_node<<<BN_, 256>>>(x, vl0w, vl0b, 0,
                         vw1 + 8192, vb1 + 128, vw2 + 8192, vb2 + 128,
                         vw3 + 8192, vb3 + 128, vw4 + 8192, vb4 + 128);
    F2<<<G, 256>>>(adj, el0w, el0b, ew + 8192, eb + 128, e1w);
    k_fin2<<<1, 64>>>(ebng + 128, ebnb + 128);

    // final: stream z2 + P2 -> out (diag zeroed inside)
    k_last<<<G, 256>>>(e1w, e1b, out);
}

// round 16
// speedup vs baseline: 1.1996x; 1.0350x over previous
#include <cuda_runtime.h>
#include <cuda_fp16.h>
#include <math_constants.h>
#include <cstdint>

// ---------------------------------------------------------------------------
// DIMES dense encoder, B=16, N=200, U=64, L=3
// w_l = w0(adj rank-1) + sum_i lrelu(bn_i(z_i)); z_i fp16.
// F2 pre-projects w2 onto e1w (P2); k_last streams z2 in dense tile blocks.
// R16: fast sigmoid, pre-converted tf32 A-tile, vectorized k_node GEMV.
// ---------------------------------------------------------------------------

constexpr int B_ = 16, N_ = 200, M_ = 199, U_ = 64;
constexpr int BN_ = B_ * N_;                     // 3200
constexpr long long E_ = (long long)BN_ * M_;    // 636800
constexpr float EPS_ = 1e-5f;
constexpr int NSLOT = 16;

__device__ __align__(16) __half g_z16[3][(size_t)636800 * 64];
__device__ __align__(16) float g_P2[(size_t)636800];
__device__ __align__(16) float g_h[BN_ * U_];
__device__ __align__(16) float g_x1[BN_ * U_];
__device__ __align__(16) float g_x2[BN_ * U_];
__device__ __align__(16) float g_x3[BN_ * U_];
__device__ __align__(16) float g_x4[BN_ * U_];
__device__ unsigned g_pooled_u[BN_ * U_];
__device__ double g_estats[NSLOT][2][U_];        // per-slot stats
__device__ __align__(16) float g_ecoef[3][2][U_];
__device__ __align__(16) float g_hcoef[2 * U_];

__device__ __forceinline__ float lrelu(float v) { return v >= 0.f ? v : 0.01f * v; }

__device__ __forceinline__ unsigned enc_f(float f) {
    unsigned u = __float_as_uint(f);
    return u ^ ((u & 0x80000000u) ? 0xffffffffu : 0x80000000u);
}
__device__ __forceinline__ float dec_f(unsigned k) {
    return __uint_as_float((k & 0x80000000u) ? (k ^ 0x80000000u) : ~k);
}

__device__ __forceinline__ unsigned to_tf32(float f) {
    unsigned r;
    asm("cvt.rna.tf32.f32 %0, %1;" : "=r"(r) : "f"(f));
    return r;
}
__device__ __forceinline__ float tf32f(float f) {
    return __uint_as_float(to_tf32(f));
}

__device__ __forceinline__ void mma_tf32(float c[4], unsigned a0, unsigned a1,
                                         unsigned a2, unsigned a3,
                                         unsigned b0, unsigned b1) {
    asm volatile(
        "mma.sync.aligned.m16n8k8.row.col.f32.tf32.tf32.f32 "
        "{%0,%1,%2,%3}, {%4,%5,%6,%7}, {%8,%9}, {%0,%1,%2,%3};"
        : "+f"(c[0]), "+f"(c[1]), "+f"(c[2]), "+f"(c[3])
        : "r"(a0), "r"(a1), "r"(a2), "r"(a3), "r"(b0), "r"(b1));
}

// C(64x64) = W(tf32 bits in smem stride 68) @ E(tf32 smem [k][u] stride 72)
__device__ __forceinline__ void do_gemm(const float* __restrict__ W,
                                        const float* __restrict__ Em,
                                        float cf[4][4], int la, int ncol0, int tig) {
    const int grp = (threadIdx.x & 31) >> 2;
#pragma unroll
    for (int nt = 0; nt < 4; nt++) { cf[nt][0]=0.f; cf[nt][1]=0.f; cf[nt][2]=0.f; cf[nt][3]=0.f; }
#pragma unroll
    for (int k0 = 0; k0 < 64; k0 += 8) {
        unsigned a0 = __float_as_uint(W[la * 68 + k0 + tig]);
        unsigned a1 = __float_as_uint(W[(la + 8) * 68 + k0 + tig]);
        unsigned a2 = __float_as_uint(W[la * 68 + k0 + tig + 4]);
        unsigned a3 = __float_as_uint(W[(la + 8) * 68 + k0 + tig + 4]);
#pragma unroll
        for (int nt = 0; nt < 4; nt++) {
            int col = ncol0 + nt * 8 + grp;
            unsigned b0 = __float_as_uint(Em[(k0 + tig) * 72 + col]);
            unsigned b1 = __float_as_uint(Em[(k0 + tig + 4) * 72 + col]);
            mma_tf32(cf[nt], a0, a1, a2, a3, b0, b1);
        }
    }
}

// ---------------------------------------------------------------------------
// Edge kernel: grid = BN_*4, one block per (bn, 64-row tile), 256 threads.
// ---------------------------------------------------------------------------
template<int NZ, bool POOLED, bool PROJ>
__global__ void __launch_bounds__(256) k_edge(
    const float* __restrict__ adj, const float* __restrict__ ew0, const float* __restrict__ eb0,
    const float* __restrict__ Ew,  const float* __restrict__ Eb,
    const float* __restrict__ e1w)
{
    __shared__ float W_sh[64 * 68];
    __shared__ float e_sh[64 * 72];   // E for GEMM; reused as z staging
    __shared__ float zc_sh[64];
    __shared__ float ssum[64], ssq[64];
    __shared__ unsigned pool_sh[64];
    __shared__ float adj_sh[64];

    const int bid = blockIdx.x;
    const int bn = bid >> 2, tile = bid & 3;
    const int m0 = tile * 64;
    const int n = bn % N_, b = bn / N_;
    const int t = threadIdx.x;
    const int c = t & 15, r = t >> 4, c4 = c * 4;
    const int lane = t & 31, wp = t >> 5, grp = lane >> 2, tig = lane & 3;
    const int la = (wp & 3) * 16 + grp;
    const int lb = la + 8;
    const int ncol0 = (wp >> 2) * 32;
    const int slot = bid & (NSLOT - 1);

    if (t < 64) {
        int m = m0 + t;
        int dst = m + (m >= n);
        adj_sh[t] = (m < M_) ? __ldg(&adj[(size_t)bn * N_ + dst]) : 0.f;
        zc_sh[t] = __ldg(&Eb[t]) + g_x3[bn * U_ + t];
        ssum[t] = 0.f; ssq[t] = 0.f;
        if (POOLED) pool_sh[t] = 0u;
    }
    for (int idx = t; idx < 1024; idx += 256) {
        int k = idx >> 4, q = (idx & 15) * 4;
        float4 v = __ldg((const float4*)&Ew[k * 64 + q]);
        v.x = tf32f(v.x); v.y = tf32f(v.y);
        v.z = tf32f(v.z); v.w = tf32f(v.w);
        *(float4*)&e_sh[k * 72 + q] = v;
    }
    __syncthreads();

    // --- build w0 in registers (rows 4r+j, cols c4..c4+3) ---
    float4 ew04 = __ldg((const float4*)&ew0[c4]);
    float4 eb04 = __ldg((const float4*)&eb0[c4]);
    float4 w4[4];
#pragma unroll
    for (int j = 0; j < 4; j++) {
        float a = adj_sh[4 * r + j];
        w4[j].x = lrelu(fmaf(a, ew04.x, eb04.x));
        w4[j].y = lrelu(fmaf(a, ew04.y, eb04.y));
        w4[j].z = lrelu(fmaf(a, ew04.z, eb04.z));
        w4[j].w = lrelu(fmaf(a, ew04.w, eb04.w));
    }

    // --- apply previous layers' residuals from fp16 z (coalesced loads) ---
#pragma unroll
    for (int i = 0; i < NZ; i++) {
        float4 s4 = *(const float4*)&g_ecoef[i][0][c4];
        float4 f4 = *(const float4*)&g_ecoef[i][1][c4];
        const __half* zb = g_z16[i] + (size_t)bn * M_ * U_;
#pragma unroll
        for (int j = 0; j < 4; j++) {
            int m = m0 + 4 * r + j;
            if (m < M_) {
                uint2 zr = *(const uint2*)&zb[(size_t)m * U_ + c4];
                float2 za = __half22float2(*(__half2*)&zr.x);
                float2 zz = __half22float2(*(__half2*)&zr.y);
                w4[j].x += lrelu(fmaf(za.x, s4.x, f4.x));
                w4[j].y += lrelu(fmaf(za.y, s4.y, f4.y));
                w4[j].z += lrelu(fmaf(zz.x, s4.z, f4.z));
                w4[j].w += lrelu(fmaf(zz.y, s4.w, f4.w));
            }
        }
    }

    if (PROJ) {
        // partial projection of current w onto e1w -> g_P2 (no bias)
        float4 e1 = __ldg((const float4*)&e1w[c4]);
        float pj[4];
#pragma unroll
        for (int j = 0; j < 4; j++)
            pj[j] = w4[j].x * e1.x + w4[j].y * e1.y + w4[j].z * e1.z + w4[j].w * e1.w;
#pragma unroll
        for (int off = 1; off <= 8; off <<= 1) {
#pragma unroll
            for (int j = 0; j < 4; j++)
                pj[j] += __shfl_xor_sync(0xffffffffu, pj[j], off);
        }
        if (c == 0) {
#pragma unroll
            for (int j = 0; j < 4; j++) {
                int m = m0 + 4 * r + j;
                if (m < M_) g_P2[(size_t)bn * M_ + m] = pj[j];
            }
        }
    }

    const float* x2b = &g_x2[(size_t)b * N_ * U_];
    const float* x4b = &g_x4[(size_t)b * N_ * U_];

    // pooled pre-GEMM: register w, coalesced x2 row loads, fast sigmoid
    float4 pool4 = make_float4(-CUDART_INF_F, -CUDART_INF_F, -CUDART_INF_F, -CUDART_INF_F);
    if (POOLED) {
#pragma unroll
        for (int j = 0; j < 4; j++) {
            int m = m0 + 4 * r + j;
            if (m < M_) {
                int dst = m + (m >= n);
                float4 x2v = __ldg((const float4*)&x2b[dst * U_ + c4]);
                pool4.x = fmaxf(pool4.x, __fdividef(x2v.x, 1.f + __expf(-w4[j].x)));
                pool4.y = fmaxf(pool4.y, __fdividef(x2v.y, 1.f + __expf(-w4[j].y)));
                pool4.z = fmaxf(pool4.z, __fdividef(x2v.z, 1.f + __expf(-w4[j].z)));
                pool4.w = fmaxf(pool4.w, __fdividef(x2v.w, 1.f + __expf(-w4[j].w)));
            }
        }
    }

    // stash w (pre-converted to tf32 bits) to smem for GEMM A-fragments
#pragma unroll
    for (int j = 0; j < 4; j++) {
        float4 wt;
        wt.x = tf32f(w4[j].x); wt.y = tf32f(w4[j].y);
        wt.z = tf32f(w4[j].z); wt.w = tf32f(w4[j].w);
        *(float4*)&W_sh[(4 * r + j) * 68 + c4] = wt;
    }
    __syncthreads();

    float cf[4][4];
    do_gemm(W_sh, e_sh, cf, la, ncol0, tig);
    __syncthreads();   // all GEMM reads of e_sh done

    // stage z fragments into e_sh (now dead), stride 68
#pragma unroll
    for (int nt = 0; nt < 4; nt++) {
        int cc = ncol0 + nt * 8 + 2 * tig;
        *(float2*)&e_sh[la * 68 + cc] = make_float2(cf[nt][0], cf[nt][1]);
        *(float2*)&e_sh[lb * 68 + cc] = make_float2(cf[nt][2], cf[nt][3]);
    }
    __syncthreads();

    // coalesced epilogue in (r,c) mapping
    __half* zo = g_z16[NZ] + (size_t)bn * M_ * U_;
    float4 zc4 = *(const float4*)&zc_sh[c4];
    float4 esum = make_float4(0.f, 0.f, 0.f, 0.f);
    float4 esq  = make_float4(0.f, 0.f, 0.f, 0.f);
#pragma unroll
    for (int j = 0; j < 4; j++) {
        int rr = 4 * r + j, m = m0 + rr;
        if (m < M_) {
            int dst = m + (m >= n);
            float4 z4 = *(const float4*)&e_sh[rr * 68 + c4];
            float4 x4v = __ldg((const float4*)&x4b[dst * U_ + c4]);
            z4.x += zc4.x + x4v.x;
            z4.y += zc4.y + x4v.y;
            z4.z += zc4.z + x4v.z;
            z4.w += zc4.w + x4v.w;
            uint2 zp;
            *(__half2*)&zp.x = __floats2half2_rn(z4.x, z4.y);
            *(__half2*)&zp.y = __floats2half2_rn(z4.z, z4.w);
            *(uint2*)&zo[(size_t)m * U_ + c4] = zp;
            esum.x += z4.x; esq.x = fmaf(z4.x, z4.x, esq.x);
            esum.y += z4.y; esq.y = fmaf(z4.y, z4.y, esq.y);
            esum.z += z4.z; esq.z = fmaf(z4.z, z4.z, esq.z);
            esum.w += z4.w; esq.w = fmaf(z4.w, z4.w, esq.w);
        }
    }

    // reduce over the two r-values per warp, then smem atomics
    esum.x += __shfl_xor_sync(0xffffffffu, esum.x, 16);
    esum.y += __shfl_xor_sync(0xffffffffu, esum.y, 16);
    esum.z += __shfl_xor_sync(0xffffffffu, esum.z, 16);
    esum.w += __shfl_xor_sync(0xffffffffu, esum.w, 16);
    esq.x  += __shfl_xor_sync(0xffffffffu, esq.x, 16);
    esq.y  += __shfl_xor_sync(0xffffffffu, esq.y, 16);
    esq.z  += __shfl_xor_sync(0xffffffffu, esq.z, 16);
    esq.w  += __shfl_xor_sync(0xffffffffu, esq.w, 16);
    if (POOLED) {
        pool4.x = fmaxf(pool4.x, __shfl_xor_sync(0xffffffffu, pool4.x, 16));
        pool4.y = fmaxf(pool4.y, __shfl_xor_sync(0xffffffffu, pool4.y, 16));
        pool4.z = fmaxf(pool4.z, __shfl_xor_sync(0xffffffffu, pool4.z, 16));
        pool4.w = fmaxf(pool4.w, __shfl_xor_sync(0xffffffffu, pool4.w, 16));
    }
    if (lane < 16) {
        atomicAdd(&ssum[c4 + 0], esum.x); atomicAdd(&ssum[c4 + 1], esum.y);
        atomicAdd(&ssum[c4 + 2], esum.z); atomicAdd(&ssum[c4 + 3], esum.w);
        atomicAdd(&ssq[c4 + 0], esq.x);   atomicAdd(&ssq[c4 + 1], esq.y);
        atomicAdd(&ssq[c4 + 2], esq.z);   atomicAdd(&ssq[c4 + 3], esq.w);
        if (POOLED) {
            atomicMax(&pool_sh[c4 + 0], enc_f(pool4.x));
            atomicMax(&pool_sh[c4 + 1], enc_f(pool4.y));
            atomicMax(&pool_sh[c4 + 2], enc_f(pool4.z));
            atomicMax(&pool_sh[c4 + 3], enc_f(pool4.w));
        }
    }
    __syncthreads();
    if (t < 64) {
        atomicAdd(&g_estats[slot][0][t], (double)ssum[t]);
        atomicAdd(&g_estats[slot][1][t], (double)ssq[t]);
        if (POOLED) atomicMax(&g_pooled_u[bn * U_ + t], pool_sh[t]);
    }
}

// final: out = P2 + dot(lrelu(bn2(z2)), e1w) + e1b.
// Dense tile blocks: grid = BN_*4. Diag zeroed by tile 0 thread 0.
__global__ void __launch_bounds__(256) k_last(const float* __restrict__ e1w,
                                              const float* __restrict__ e1b,
                                              float* __restrict__ out) {
    const int bid = blockIdx.x;
    const int bn = bid >> 2, tile = bid & 3;
    const int m0 = tile * 64;
    const int n = bn % N_;
    const int t = threadIdx.x;
    const int c = t & 15, r = t >> 4, c4 = c * 4;

    if (tile == 0 && t == 0) out[(size_t)bn * N_ + n] = 0.f;

    float4 e1 = __ldg((const float4*)&e1w[c4]);
    float4 s4 = *(const float4*)&g_ecoef[2][0][c4];
    float4 f4 = *(const float4*)&g_ecoef[2][1][c4];
    const __half* zb = g_z16[2] + (size_t)bn * M_ * U_;

    float pj[4];
#pragma unroll
    for (int j = 0; j < 4; j++) {
        int m = m0 + 4 * r + j;
        pj[j] = 0.f;
        if (m < M_) {
            uint2 zr = *(const uint2*)&zb[(size_t)m * U_ + c4];
            float2 za = __half22float2(*(__half2*)&zr.x);
            float2 zz = __half22float2(*(__half2*)&zr.y);
            float a0 = lrelu(fmaf(za.x, s4.x, f4.x));
            float a1 = lrelu(fmaf(za.y, s4.y, f4.y));
            float a2 = lrelu(fmaf(zz.x, s4.z, f4.z));
            float a3 = lrelu(fmaf(zz.y, s4.w, f4.w));
            pj[j] = a0 * e1.x + a1 * e1.y + a2 * e1.z + a3 * e1.w;
        }
    }
#pragma unroll
    for (int off = 1; off <= 8; off <<= 1) {
#pragma unroll
        for (int j = 0; j < 4; j++)
            pj[j] += __shfl_xor_sync(0xffffffffu, pj[j], off);
    }
    if (c == 0) {
        float bias = __ldg(&e1b[0]);
#pragma unroll
        for (int j = 0; j < 4; j++) {
            int m = m0 + 4 * r + j;
            if (m < M_) {
                int dst = m + (m >= n);
                out[(size_t)bn * N_ + dst] =
                    pj[j] + g_P2[(size_t)bn * M_ + m] + bias;
            }
        }
    }
}

// node path: h init/update + x1..x4 GEMVs (vectorized). One block per bn.
// thread t: mat = t>>6, cg = (t&63)&15 (4 cols), kp = (t&63)>>4 (16-wide k part)
__global__ void __launch_bounds__(256) k_node(
    const float* __restrict__ x, const float* __restrict__ l0w, const float* __restrict__ l0b,
    int first,
    const float* __restrict__ w1, const float* __restrict__ b1,
    const float* __restrict__ w2, const float* __restrict__ b2,
    const float* __restrict__ w3, const float* __restrict__ b3,
    const float* __restrict__ w4, const float* __restrict__ b4)
{
    __shared__ float hsh[U_];
    __shared__ float red[4][16][4];
    int bn = blockIdx.x, t = threadIdx.x;
    if (t < U_) {
        float hv;
        if (first) {
            hv = lrelu(x[bn * 2] * __ldg(&l0w[t]) + x[bn * 2 + 1] * __ldg(&l0w[U_ + t]) + __ldg(&l0b[t]));
        } else {
            float zh = g_x1[bn * U_ + t] + dec_f(g_pooled_u[bn * U_ + t]);
            hv = g_h[bn * U_ + t] + lrelu(fmaf(zh, g_hcoef[t], g_hcoef[U_ + t]));
        }
        hsh[t] = hv;
        g_h[bn * U_ + t] = hv;
        g_pooled_u[bn * U_ + t] = 0u;   // reset for this layer's pooling
    }
    __syncthreads();

    const int mat = t >> 6, local = t & 63;
    const int cg = local & 15, kp = local >> 4;
    const int lane = t & 31, wp = t >> 5;
    const float* W; const float* bb; float* xout;
    switch (mat) {
        case 0:  W = w1; bb = b1; xout = g_x1; break;
        case 1:  W = w2; bb = b2; xout = g_x2; break;
        case 2:  W = w3; bb = b3; xout = g_x3; break;
        default: W = w4; bb = b4; xout = g_x4; break;
    }
    float acc[4] = {0.f, 0.f, 0.f, 0.f};
    const int k0 = kp * 16;
#pragma unroll
    for (int i = 0; i < 16; i++) {
        float hk = hsh[k0 + i];
        float4 wv = __ldg((const float4*)&W[(k0 + i) * U_ + cg * 4]);
        acc[0] = fmaf(hk, wv.x, acc[0]);
        acc[1] = fmaf(hk, wv.y, acc[1]);
        acc[2] = fmaf(hk, wv.z, acc[2]);
        acc[3] = fmaf(hk, wv.w, acc[3]);
    }
    // combine kp pairs within warp (lane bit 4 = kp low bit)
#pragma unroll
    for (int j = 0; j < 4; j++)
        acc[j] += __shfl_xor_sync(0xffffffffu, acc[j], 16);
    // cross-warp combine via smem: even warp stores, odd warp finishes
    if (lane < 16 && (wp & 1) == 0) {
        red[mat][cg][0] = acc[0]; red[mat][cg][1] = acc[1];
        red[mat][cg][2] = acc[2]; red[mat][cg][3] = acc[3];
    }
    __syncthreads();
    if (lane < 16 && (wp & 1) == 1) {
        float4 b4v = __ldg((const float4*)&bb[cg * 4]);
        float4 o;
        o.x = red[mat][cg][0] + acc[0] + b4v.x;
        o.y = red[mat][cg][1] + acc[1] + b4v.y;
        o.z = red[mat][cg][2] + acc[2] + b4v.z;
        o.w = red[mat][cg][3] + acc[3] + b4v.w;
        *(float4*)&xout[bn * U_ + cg * 4] = o;
    }
}

// fused h-stats + finalize for layer l: 64 blocks (one per u).
__global__ void __launch_bounds__(256) k_hfin(int l,
        const float* __restrict__ hg, const float* __restrict__ hb,
        const float* __restrict__ eg, const float* __restrict__ eb) {
    __shared__ float rs[256], rq[256];
    int u = blockIdx.x, t = threadIdx.x;
    float s = 0.f, q = 0.f;
    for (int i = t; i < BN_; i += 256) {
        float v = g_x1[i * U_ + u] + dec_f(g_pooled_u[i * U_ + u]);
        s += v; q = fmaf(v, v, q);
    }
    rs[t] = s; rq[t] = q;
    __syncthreads();
    for (int off = 128; off >= 1; off >>= 1) {
        if (t < off) { rs[t] += rs[t + off]; rq[t] += rq[t + off]; }
        __syncthreads();
    }
    if (t == 0) {
        float hmean = rs[0] / (float)BN_;
        float hvar  = rq[0] / (float)BN_ - hmean * hmean;
        float hs = __ldg(&hg[u]) * rsqrtf(hvar + EPS_);
        g_hcoef[u] = hs;
        g_hcoef[U_ + u] = __ldg(&hb[u]) - hmean * hs;

        double es = 0.0, eq2 = 0.0;
#pragma unroll
        for (int sl = 0; sl < NSLOT; sl++) {
            es += g_estats[sl][0][u]; eq2 += g_estats[sl][1][u];
            g_estats[sl][0][u] = 0.0; g_estats[sl][1][u] = 0.0;
        }
        float emean = (float)(es / (double)E_);
        float evar  = (float)(eq2 / (double)E_) - emean * emean;
        float esc = __ldg(&eg[u]) * rsqrtf(evar + EPS_);
        g_ecoef[l][0][u] = esc;
        g_ecoef[l][1][u] = __ldg(&eb[u]) - emean * esc;
    }
}

// layer-2 finalize (ecoef only)
__global__ void k_fin2(const float* __restrict__ eg, const float* __restrict__ eb) {
    int u = threadIdx.x;  // 64
    double es = 0.0, eq = 0.0;
#pragma unroll
    for (int sl = 0; sl < NSLOT; sl++) {
        es += g_estats[sl][0][u]; eq += g_estats[sl][1][u];
        g_estats[sl][0][u] = 0.0; g_estats[sl][1][u] = 0.0;
    }
    float emean = (float)(es / (double)E_);
    float evar  = (float)(eq / (double)E_) - emean * emean;
    float esc = eg[u] * rsqrtf(evar + EPS_);
    g_ecoef[2][0][u] = esc;
    g_ecoef[2][1][u] = eb[u] - emean * esc;
}

extern "C" void kernel_launch(void* const* d_in, const int* in_sizes, int n_in,
                              void* d_out, int out_size) {
    const float* x    = (const float*)d_in[0];
    const float* adj  = (const float*)d_in[1];
    const float* vl0w = (const float*)d_in[2];
    const float* vl0b = (const float*)d_in[3];
    const float* vw1  = (const float*)d_in[4];
    const float* vb1  = (const float*)d_in[5];
    const float* vw2  = (const float*)d_in[6];
    const float* vb2  = (const float*)d_in[7];
    const float* vw3  = (const float*)d_in[8];
    const float* vb3  = (const float*)d_in[9];
    const float* vw4  = (const float*)d_in[10];
    const float* vb4  = (const float*)d_in[11];
    const float* vbng = (const float*)d_in[12];
    const float* vbnb = (const float*)d_in[13];
    const float* el0w = (const float*)d_in[14];
    const float* el0b = (const float*)d_in[15];
    const float* ew   = (const float*)d_in[16];
    const float* eb   = (const float*)d_in[17];
    const float* ebng = (const float*)d_in[18];
    const float* ebnb = (const float*)d_in[19];
    const float* e1w  = (const float*)d_in[20];
    const float* e1b  = (const float*)d_in[21];
    float* out = (float*)d_out;

    auto S0 = k_edge<0, true,  false>;
    auto F1 = k_edge<1, true,  false>;
    auto F2 = k_edge<2, false, true >;   // + P2 projection
    const int G = BN_ * 4;

    // layer 0
    k_node<<<BN_, 256>>>(x, vl0w, vl0b, 1,
                         vw1, vb1, vw2, vb2, vw3, vb3, vw4, vb4);
    S0<<<G, 256>>>(adj, el0w, el0b, ew, eb, nullptr);
    k_hfin<<<64, 256>>>(0, vbng, vbnb, ebng, ebnb);

    // layer 1
    k_node<<<BN_, 256>>>(x, vl0w, vl0b, 0,
                         vw1 + 4096, vb1 + 64, vw2 + 4096, vb2 + 64,
                         vw3 + 4096, vb3 + 64, vw4 + 4096, vb4 + 64);
    F1<<<G, 256>>>(adj, el0w, el0b, ew + 4096, eb + 64, nullptr);
    k_hfin<<<64, 256>>>(1, vbng + 64, vbnb + 64, ebng + 64, ebnb + 64);

    // layer 2
    k_node<<<BN_, 256>>>(x, vl0w, vl0b, 0,
                         vw1 + 8192, vb1 + 128, vw2 + 8192, vb2 + 128,
                         vw3 + 8192, vb3 + 128, vw4 + 8192, vb4 + 128);
    F2<<<G, 256>>>(adj, el0w, el0b, ew + 8192, eb + 128, e1w);
    k_fin2<<<1, 64>>>(ebng + 128, ebnb + 128);

    // final: stream z2 + P2 -> out (diag zeroed inside)
    k_last<<<G, 256>>>(e1w, e1b, out);
}

// round 17
// speedup vs baseline: 1.2909x; 1.0761x over previous
#include <cuda_runtime.h>
#include <cuda_fp16.h>
#include <math_constants.h>
#include <cstdint>

// ---------------------------------------------------------------------------
// DIMES dense encoder, B=16, N=200, U=64, L=3
// w_l = w0(adj rank-1) + sum_i lrelu(bn_i(z_i)); z_i fp16.
// R17: fp16 GEMM (m16n8k16) with conflict-free k-pair-packed half2 layouts.
// ---------------------------------------------------------------------------

constexpr int B_ = 16, N_ = 200, M_ = 199, U_ = 64;
constexpr int BN_ = B_ * N_;                     // 3200
constexpr long long E_ = (long long)BN_ * M_;    // 636800
constexpr float EPS_ = 1e-5f;
constexpr int NSLOT = 16;

__device__ __align__(16) __half g_z16[3][(size_t)636800 * 64];
__device__ __align__(16) float g_P2[(size_t)636800];
__device__ __align__(16) float g_h[BN_ * U_];
__device__ __align__(16) float g_x1[BN_ * U_];
__device__ __align__(16) float g_x2[BN_ * U_];
__device__ __align__(16) float g_x3[BN_ * U_];
__device__ __align__(16) float g_x4[BN_ * U_];
__device__ unsigned g_pooled_u[BN_ * U_];
__device__ double g_estats[NSLOT][2][U_];        // per-slot stats
__device__ __align__(16) float g_ecoef[3][2][U_];
__device__ __align__(16) float g_hcoef[2 * U_];

__device__ __forceinline__ float lrelu(float v) { return v >= 0.f ? v : 0.01f * v; }

__device__ __forceinline__ unsigned enc_f(float f) {
    unsigned u = __float_as_uint(f);
    return u ^ ((u & 0x80000000u) ? 0xffffffffu : 0x80000000u);
}
__device__ __forceinline__ float dec_f(unsigned k) {
    return __uint_as_float((k & 0x80000000u) ? (k ^ 0x80000000u) : ~k);
}

__device__ __forceinline__ void mma16(float c[4], unsigned a0, unsigned a1,
                                      unsigned a2, unsigned a3,
                                      unsigned b0, unsigned b1) {
    asm volatile(
        "mma.sync.aligned.m16n8k16.row.col.f32.f16.f16.f32 "
        "{%0,%1,%2,%3}, {%4,%5,%6,%7}, {%8,%9}, {%0,%1,%2,%3};"
        : "+f"(c[0]), "+f"(c[1]), "+f"(c[2]), "+f"(c[3])
        : "r"(a0), "r"(a1), "r"(a2), "r"(a3), "r"(b0), "r"(b1));
}

// C(64x64) = W(fp16, W2[row][kk] stride 36 half2) @ E(fp16, E2[kk][col] stride 72 half2)
// kk packs k-pairs: entry = (val[2kk], val[2kk+1]). Conflict-free on both operands.
__device__ __forceinline__ void do_gemm16(const __half2* __restrict__ W2,
                                          const __half2* __restrict__ E2,
                                          float cf[4][4], int la, int ncol0, int tig) {
    const int grp = (threadIdx.x & 31) >> 2;
#pragma unroll
    for (int nt = 0; nt < 4; nt++) { cf[nt][0]=0.f; cf[nt][1]=0.f; cf[nt][2]=0.f; cf[nt][3]=0.f; }
#pragma unroll
    for (int kk0 = 0; kk0 < 32; kk0 += 8) {   // 8 half2 = k16 per step
        unsigned a0 = *(const unsigned*)&W2[la * 36 + kk0 + tig];
        unsigned a1 = *(const unsigned*)&W2[(la + 8) * 36 + kk0 + tig];
        unsigned a2 = *(const unsigned*)&W2[la * 36 + kk0 + 4 + tig];
        unsigned a3 = *(const unsigned*)&W2[(la + 8) * 36 + kk0 + 4 + tig];
#pragma unroll
        for (int nt = 0; nt < 4; nt++) {
            int col = ncol0 + nt * 8 + grp;
            unsigned b0 = *(const unsigned*)&E2[(kk0 + tig) * 72 + col];
            unsigned b1 = *(const unsigned*)&E2[(kk0 + 4 + tig) * 72 + col];
            mma16(cf[nt], a0, a1, a2, a3, b0, b1);
        }
    }
}

// ---------------------------------------------------------------------------
// Edge kernel: grid = BN_*4, one block per (bn, 64-row tile), 256 threads.
// ---------------------------------------------------------------------------
template<int NZ, bool POOLED, bool PROJ>
__global__ void __launch_bounds__(256) k_edge(
    const float* __restrict__ adj, const float* __restrict__ ew0, const float* __restrict__ eb0,
    const float* __restrict__ Ew,  const float* __restrict__ Eb,
    const float* __restrict__ e1w)
{
    __shared__ __align__(16) float sm_pool[4608];   // W2(2304) + E2(2304); z staging after GEMM
    __shared__ float zc_sh[64];
    __shared__ float ssum[64], ssq[64];
    __shared__ unsigned pool_sh[64];
    __shared__ float adj_sh[64];

    __half2* W2 = (__half2*)sm_pool;             // [64][36]
    __half2* E2 = (__half2*)(sm_pool + 2304);    // [32][72]

    const int bid = blockIdx.x;
    const int bn = bid >> 2, tile = bid & 3;
    const int m0 = tile * 64;
    const int n = bn % N_, b = bn / N_;
    const int t = threadIdx.x;
    const int c = t & 15, r = t >> 4, c4 = c * 4;
    const int lane = t & 31, wp = t >> 5, grp = lane >> 2, tig = lane & 3;
    const int la = (wp & 3) * 16 + grp;
    const int lb = la + 8;
    const int ncol0 = (wp >> 2) * 32;
    const int slot = bid & (NSLOT - 1);

    if (t < 64) {
        int m = m0 + t;
        int dst = m + (m >= n);
        adj_sh[t] = (m < M_) ? __ldg(&adj[(size_t)bn * N_ + dst]) : 0.f;
        zc_sh[t] = __ldg(&Eb[t]) + g_x3[bn * U_ + t];
        ssum[t] = 0.f; ssq[t] = 0.f;
        if (POOLED) pool_sh[t] = 0u;
    }
    // E -> E2 (k-pair-packed fp16): E2[kk][u] = (E[2kk][u], E[2kk+1][u])
    for (int idx = t; idx < 2048; idx += 256) {
        int kk = idx >> 6, u = idx & 63;
        float e0 = __ldg(&Ew[(2 * kk) * 64 + u]);
        float e1 = __ldg(&Ew[(2 * kk + 1) * 64 + u]);
        E2[kk * 72 + u] = __floats2half2_rn(e0, e1);
    }
    __syncthreads();

    // --- build w0 in registers (rows 4r+j, cols c4..c4+3) ---
    float4 ew04 = __ldg((const float4*)&ew0[c4]);
    float4 eb04 = __ldg((const float4*)&eb0[c4]);
    float4 w4[4];
#pragma unroll
    for (int j = 0; j < 4; j++) {
        float a = adj_sh[4 * r + j];
        w4[j].x = lrelu(fmaf(a, ew04.x, eb04.x));
        w4[j].y = lrelu(fmaf(a, ew04.y, eb04.y));
        w4[j].z = lrelu(fmaf(a, ew04.z, eb04.z));
        w4[j].w = lrelu(fmaf(a, ew04.w, eb04.w));
    }

    // --- apply previous layers' residuals from fp16 z (coalesced loads) ---
#pragma unroll
    for (int i = 0; i < NZ; i++) {
        float4 s4 = *(const float4*)&g_ecoef[i][0][c4];
        float4 f4 = *(const float4*)&g_ecoef[i][1][c4];
        const __half* zb = g_z16[i] + (size_t)bn * M_ * U_;
#pragma unroll
        for (int j = 0; j < 4; j++) {
            int m = m0 + 4 * r + j;
            if (m < M_) {
                uint2 zr = *(const uint2*)&zb[(size_t)m * U_ + c4];
                float2 za = __half22float2(*(__half2*)&zr.x);
                float2 zz = __half22float2(*(__half2*)&zr.y);
                w4[j].x += lrelu(fmaf(za.x, s4.x, f4.x));
                w4[j].y += lrelu(fmaf(za.y, s4.y, f4.y));
                w4[j].z += lrelu(fmaf(zz.x, s4.z, f4.z));
                w4[j].w += lrelu(fmaf(zz.y, s4.w, f4.w));
            }
        }
    }

    if (PROJ) {
        float4 e1 = __ldg((const float4*)&e1w[c4]);
        float pj[4];
#pragma unroll
        for (int j = 0; j < 4; j++)
            pj[j] = w4[j].x * e1.x + w4[j].y * e1.y + w4[j].z * e1.z + w4[j].w * e1.w;
#pragma unroll
        for (int off = 1; off <= 8; off <<= 1) {
#pragma unroll
            for (int j = 0; j < 4; j++)
                pj[j] += __shfl_xor_sync(0xffffffffu, pj[j], off);
        }
        if (c == 0) {
#pragma unroll
            for (int j = 0; j < 4; j++) {
                int m = m0 + 4 * r + j;
                if (m < M_) g_P2[(size_t)bn * M_ + m] = pj[j];
            }
        }
    }

    const float* x2b = &g_x2[(size_t)b * N_ * U_];
    const float* x4b = &g_x4[(size_t)b * N_ * U_];

    // pooled pre-GEMM: register w, coalesced x2 loads, fast sigmoid
    float4 pool4 = make_float4(-CUDART_INF_F, -CUDART_INF_F, -CUDART_INF_F, -CUDART_INF_F);
    if (POOLED) {
#pragma unroll
        for (int j = 0; j < 4; j++) {
            int m = m0 + 4 * r + j;
            if (m < M_) {
                int dst = m + (m >= n);
                float4 x2v = __ldg((const float4*)&x2b[dst * U_ + c4]);
                pool4.x = fmaxf(pool4.x, __fdividef(x2v.x, 1.f + __expf(-w4[j].x)));
                pool4.y = fmaxf(pool4.y, __fdividef(x2v.y, 1.f + __expf(-w4[j].y)));
                pool4.z = fmaxf(pool4.z, __fdividef(x2v.z, 1.f + __expf(-w4[j].z)));
                pool4.w = fmaxf(pool4.w, __fdividef(x2v.w, 1.f + __expf(-w4[j].w)));
            }
        }
    }

    // stash w (fp16 k-pair-packed) into W2 for GEMM A-fragments
#pragma unroll
    for (int j = 0; j < 4; j++) {
        int base = (4 * r + j) * 36 + 2 * c;
        W2[base]     = __floats2half2_rn(w4[j].x, w4[j].y);
        W2[base + 1] = __floats2half2_rn(w4[j].z, w4[j].w);
    }
    __syncthreads();

    float cf[4][4];
    do_gemm16(W2, E2, cf, la, ncol0, tig);
    __syncthreads();   // all GEMM reads of sm_pool done

    // stage z fragments into sm_pool (now dead), stride 68
    float* zst = sm_pool;
#pragma unroll
    for (int nt = 0; nt < 4; nt++) {
        int cc = ncol0 + nt * 8 + 2 * tig;
        *(float2*)&zst[la * 68 + cc] = make_float2(cf[nt][0], cf[nt][1]);
        *(float2*)&zst[lb * 68 + cc] = make_float2(cf[nt][2], cf[nt][3]);
    }
    __syncthreads();

    // coalesced epilogue in (r,c) mapping
    __half* zo = g_z16[NZ] + (size_t)bn * M_ * U_;
    float4 zc4 = *(const float4*)&zc_sh[c4];
    float4 esum = make_float4(0.f, 0.f, 0.f, 0.f);
    float4 esq  = make_float4(0.f, 0.f, 0.f, 0.f);
#pragma unroll
    for (int j = 0; j < 4; j++) {
        int rr = 4 * r + j, m = m0 + rr;
        if (m < M_) {
            int dst = m + (m >= n);
            float4 z4 = *(const float4*)&zst[rr * 68 + c4];
            float4 x4v = __ldg((const float4*)&x4b[dst * U_ + c4]);
            z4.x += zc4.x + x4v.x;
            z4.y += zc4.y + x4v.y;
            z4.z += zc4.z + x4v.z;
            z4.w += zc4.w + x4v.w;
            uint2 zp;
            *(__half2*)&zp.x = __floats2half2_rn(z4.x, z4.y);
            *(__half2*)&zp.y = __floats2half2_rn(z4.z, z4.w);
            *(uint2*)&zo[(size_t)m * U_ + c4] = zp;
            esum.x += z4.x; esq.x = fmaf(z4.x, z4.x, esq.x);
            esum.y += z4.y; esq.y = fmaf(z4.y, z4.y, esq.y);
            esum.z += z4.z; esq.z = fmaf(z4.z, z4.z, esq.z);
            esum.w += z4.w; esq.w = fmaf(z4.w, z4.w, esq.w);
        }
    }

    // reduce over the two r-values per warp, then smem atomics
    esum.x += __shfl_xor_sync(0xffffffffu, esum.x, 16);
    esum.y += __shfl_xor_sync(0xffffffffu, esum.y, 16);
    esum.z += __shfl_xor_sync(0xffffffffu, esum.z, 16);
    esum.w += __shfl_xor_sync(0xffffffffu, esum.w, 16);
    esq.x  += __shfl_xor_sync(0xffffffffu, esq.x, 16);
    esq.y  += __shfl_xor_sync(0xffffffffu, esq.y, 16);
    esq.z  += __shfl_xor_sync(0xffffffffu, esq.z, 16);
    esq.w  += __shfl_xor_sync(0xffffffffu, esq.w, 16);
    if (POOLED) {
        pool4.x = fmaxf(pool4.x, __shfl_xor_sync(0xffffffffu, pool4.x, 16));
        pool4.y = fmaxf(pool4.y, __shfl_xor_sync(0xffffffffu, pool4.y, 16));
        pool4.z = fmaxf(pool4.z, __shfl_xor_sync(0xffffffffu, pool4.z, 16));
        pool4.w = fmaxf(pool4.w, __shfl_xor_sync(0xffffffffu, pool4.w, 16));
    }
    if (lane < 16) {
        atomicAdd(&ssum[c4 + 0], esum.x); atomicAdd(&ssum[c4 + 1], esum.y);
        atomicAdd(&ssum[c4 + 2], esum.z); atomicAdd(&ssum[c4 + 3], esum.w);
        atomicAdd(&ssq[c4 + 0], esq.x);   atomicAdd(&ssq[c4 + 1], esq.y);
        atomicAdd(&ssq[c4 + 2], esq.z);   atomicAdd(&ssq[c4 + 3], esq.w);
        if (POOLED) {
            atomicMax(&pool_sh[c4 + 0], enc_f(pool4.x));
            atomicMax(&pool_sh[c4 + 1], enc_f(pool4.y));
            atomicMax(&pool_sh[c4 + 2], enc_f(pool4.z));
            atomicMax(&pool_sh[c4 + 3], enc_f(pool4.w));
        }
    }
    __syncthreads();
    if (t < 64) {
        atomicAdd(&g_estats[slot][0][t], (double)ssum[t]);
        atomicAdd(&g_estats[slot][1][t], (double)ssq[t]);
        if (POOLED) atomicMax(&g_pooled_u[bn * U_ + t], pool_sh[t]);
    }
}

// final: out = P2 + dot(lrelu(bn2(z2)), e1w) + e1b.
// Dense tile blocks: grid = BN_*4. Diag zeroed by tile 0 thread 0.
__global__ void __launch_bounds__(256) k_last(const float* __restrict__ e1w,
                                              const float* __restrict__ e1b,
                                              float* __restrict__ out) {
    const int bid = blockIdx.x;
    const int bn = bid >> 2, tile = bid & 3;
    const int m0 = tile * 64;
    const int n = bn % N_;
    const int t = threadIdx.x;
    const int c = t & 15, r = t >> 4, c4 = c * 4;

    if (tile == 0 && t == 0) out[(size_t)bn * N_ + n] = 0.f;

    float4 e1 = __ldg((const float4*)&e1w[c4]);
    float4 s4 = *(const float4*)&g_ecoef[2][0][c4];
    float4 f4 = *(const float4*)&g_ecoef[2][1][c4];
    const __half* zb = g_z16[2] + (size_t)bn * M_ * U_;

    float pj[4];
#pragma unroll
    for (int j = 0; j < 4; j++) {
        int m = m0 + 4 * r + j;
        pj[j] = 0.f;
        if (m < M_) {
            uint2 zr = *(const uint2*)&zb[(size_t)m * U_ + c4];
            float2 za = __half22float2(*(__half2*)&zr.x);
            float2 zz = __half22float2(*(__half2*)&zr.y);
            float a0 = lrelu(fmaf(za.x, s4.x, f4.x));
            float a1 = lrelu(fmaf(za.y, s4.y, f4.y));
            float a2 = lrelu(fmaf(zz.x, s4.z, f4.z));
            float a3 = lrelu(fmaf(zz.y, s4.w, f4.w));
            pj[j] = a0 * e1.x + a1 * e1.y + a2 * e1.z + a3 * e1.w;
        }
    }
#pragma unroll
    for (int off = 1; off <= 8; off <<= 1) {
#pragma unroll
        for (int j = 0; j < 4; j++)
            pj[j] += __shfl_xor_sync(0xffffffffu, pj[j], off);
    }
    if (c == 0) {
        float bias = __ldg(&e1b[0]);
#pragma unroll
        for (int j = 0; j < 4; j++) {
            int m = m0 + 4 * r + j;
            if (m < M_) {
                int dst = m + (m >= n);
                out[(size_t)bn * N_ + dst] =
                    pj[j] + g_P2[(size_t)bn * M_ + m] + bias;
            }
        }
    }
}

// node path: h init/update + x1..x4 GEMVs (vectorized). One block per bn.
__global__ void __launch_bounds__(256) k_node(
    const float* __restrict__ x, const float* __restrict__ l0w, const float* __restrict__ l0b,
    int first,
    const float* __restrict__ w1, const float* __restrict__ b1,
    const float* __restrict__ w2, const float* __restrict__ b2,
    const float* __restrict__ w3, const float* __restrict__ b3,
    const float* __restrict__ w4, const float* __restrict__ b4)
{
    __shared__ float hsh[U_];
    __shared__ float red[4][16][4];
    int bn = blockIdx.x, t = threadIdx.x;
    if (t < U_) {
        float hv;
        if (first) {
            hv = lrelu(x[bn * 2] * __ldg(&l0w[t]) + x[bn * 2 + 1] * __ldg(&l0w[U_ + t]) + __ldg(&l0b[t]));
        } else {
            float zh = g_x1[bn * U_ + t] + dec_f(g_pooled_u[bn * U_ + t]);
            hv = g_h[bn * U_ + t] + lrelu(fmaf(zh, g_hcoef[t], g_hcoef[U_ + t]));
        }
        hsh[t] = hv;
        g_h[bn * U_ + t] = hv;
        g_pooled_u[bn * U_ + t] = 0u;   // reset for this layer's pooling
    }
    __syncthreads();

    const int mat = t >> 6, local = t & 63;
    const int cg = local & 15, kp = local >> 4;
    const int lane = t & 31, wp = t >> 5;
    const float* W; const float* bb; float* xout;
    switch (mat) {
        case 0:  W = w1; bb = b1; xout = g_x1; break;
        case 1:  W = w2; bb = b2; xout = g_x2; break;
        case 2:  W = w3; bb = b3; xout = g_x3; break;
        default: W = w4; bb = b4; xout = g_x4; break;
    }
    float acc[4] = {0.f, 0.f, 0.f, 0.f};
    const int k0 = kp * 16;
#pragma unroll
    for (int i = 0; i < 16; i++) {
        float hk = hsh[k0 + i];
        float4 wv = __ldg((const float4*)&W[(k0 + i) * U_ + cg * 4]);
        acc[0] = fmaf(hk, wv.x, acc[0]);
        acc[1] = fmaf(hk, wv.y, acc[1]);
        acc[2] = fmaf(hk, wv.z, acc[2]);
        acc[3] = fmaf(hk, wv.w, acc[3]);
    }
#pragma unroll
    for (int j = 0; j < 4; j++)
        acc[j] += __shfl_xor_sync(0xffffffffu, acc[j], 16);
    if (lane < 16 && (wp & 1) == 0) {
        red[mat][cg][0] = acc[0]; red[mat][cg][1] = acc[1];
        red[mat][cg][2] = acc[2]; red[mat][cg][3] = acc[3];
    }
    __syncthreads();
    if (lane < 16 && (wp & 1) == 1) {
        float4 b4v = __ldg((const float4*)&bb[cg * 4]);
        float4 o;
        o.x = red[mat][cg][0] + acc[0] + b4v.x;
        o.y = red[mat][cg][1] + acc[1] + b4v.y;
        o.z = red[mat][cg][2] + acc[2] + b4v.z;
        o.w = red[mat][cg][3] + acc[3] + b4v.w;
        *(float4*)&xout[bn * U_ + cg * 4] = o;
    }
}

// fused h-stats + finalize for layer l: 64 blocks (one per u).
__global__ void __launch_bounds__(256) k_hfin(int l,
        const float* __restrict__ hg, const float* __restrict__ hb,
        const float* __restrict__ eg, const float* __restrict__ eb) {
    __shared__ float rs[256], rq[256];
    int u = blockIdx.x, t = threadIdx.x;
    float s = 0.f, q = 0.f;
    for (int i = t; i < BN_; i += 256) {
        float v = g_x1[i * U_ + u] + dec_f(g_pooled_u[i * U_ + u]);
        s += v; q = fmaf(v, v, q);
    }
    rs[t] = s; rq[t] = q;
    __syncthreads();
    for (int off = 128; off >= 1; off >>= 1) {
        if (t < off) { rs[t] += rs[t + off]; rq[t] += rq[t + off]; }
        __syncthreads();
    }
    if (t == 0) {
        float hmean = rs[0] / (float)BN_;
        float hvar  = rq[0] / (float)BN_ - hmean * hmean;
        float hs = __ldg(&hg[u]) * rsqrtf(hvar + EPS_);
        g_hcoef[u] = hs;
        g_hcoef[U_ + u] = __ldg(&hb[u]) - hmean * hs;

        double es = 0.0, eq2 = 0.0;
#pragma unroll
        for (int sl = 0; sl < NSLOT; sl++) {
            es += g_estats[sl][0][u]; eq2 += g_estats[sl][1][u];
            g_estats[sl][0][u] = 0.0; g_estats[sl][1][u] = 0.0;
        }
        float emean = (float)(es / (double)E_);
        float evar  = (float)(eq2 / (double)E_) - emean * emean;
        float esc = __ldg(&eg[u]) * rsqrtf(evar + EPS_);
        g_ecoef[l][0][u] = esc;
        g_ecoef[l][1][u] = __ldg(&eb[u]) - emean * esc;
    }
}

// layer-2 finalize (ecoef only)
__global__ void k_fin2(const float* __restrict__ eg, const float* __restrict__ eb) {
    int u = threadIdx.x;  // 64
    double es = 0.0, eq = 0.0;
#pragma unroll
    for (int sl = 0; sl < NSLOT; sl++) {
        es += g_estats[sl][0][u]; eq += g_estats[sl][1][u];
        g_estats[sl][0][u] = 0.0; g_estats[sl][1][u] = 0.0;
    }
    float emean = (float)(es / (double)E_);
    float evar  = (float)(eq / (double)E_) - emean * emean;
    float esc = eg[u] * rsqrtf(evar + EPS_);
    g_ecoef[2][0][u] = esc;
    g_ecoef[2][1][u] = eb[u] - emean * esc;
}

extern "C" void kernel_launch(void* const* d_in, const int* in_sizes, int n_in,
                              void* d_out, int out_size) {
    const float* x    = (const float*)d_in[0];
    const float* adj  = (const float*)d_in[1];
    const float* vl0w = (const float*)d_in[2];
    const float* vl0b = (const float*)d_in[3];
    const float* vw1  = (const float*)d_in[4];
    const float* vb1  = (const float*)d_in[5];
    const float* vw2  = (const float*)d_in[6];
    const float* vb2  = (const float*)d_in[7];
    const float* vw3  = (const float*)d_in[8];
    const float* vb3  = (const float*)d_in[9];
    const float* vw4  = (const float*)d_in[10];
    const float* vb4  = (const float*)d_in[11];
    const float* vbng = (const float*)d_in[12];
    const float* vbnb = (const float*)d_in[13];
    const float* el0w = (const float*)d_in[14];
    const float* el0b = (const float*)d_in[15];
    const float* ew   = (const float*)d_in[16];
    const float* eb   = (const float*)d_in[17];
    const float* ebng = (const float*)d_in[18];
    const float* ebnb = (const float*)d_in[19];
    const float* e1w  = (const float*)d_in[20];
    const float* e1b  = (const float*)d_in[21];
    float* out = (float*)d_out;

    auto S0 = k_edge<0, true,  false>;
    auto F1 = k_edge<1, true,  false>;
    auto F2 = k_edge<2, false, true >;   // + P2 projection
    const int G = BN_ * 4;

    // layer 0
    k_node<<<BN_, 256>>>(x, vl0w, vl0b, 1,
                         vw1, vb1, vw2, vb2, vw3, vb3, vw4, vb4);
    S0<<<G, 256>>>(adj, el0w, el0b, ew, eb, nullptr);
    k_hfin<<<64, 256>>>(0, vbng, vbnb, ebng, ebnb);

    // layer 1
    k_node<<<BN_, 256>>>(x, vl0w, vl0b, 0,
                         vw1 + 4096, vb1 + 64, vw2 + 4096, vb2 + 64,
                         vw3 + 4096, vb3 + 64, vw4 + 4096, vb4 + 64);
    F1<<<G, 256>>>(adj, el0w, el0b, ew + 4096, eb + 64, nullptr);
    k_hfin<<<64, 256>>>(1, vbng + 64, vbnb + 64, ebng + 64, ebnb + 64);

    // layer 2
    k_node<<<BN_, 256>>>(x, vl0w, vl0b, 0,
                         vw1 + 8192, vb1 + 128, vw2 + 8192, vb2 + 128,
                         vw3 + 8192, vb3 + 128, vw4 + 8192, vb4 + 128);
    F2<<<G, 256>>>(adj, el0w, el0b, ew + 8192, eb + 128, e1w);
    k_fin2<<<1, 64>>>(ebng + 128, ebnb + 128);

    // final: stream z2 + P2 -> out (diag zeroed inside)
    k_last<<<G, 256>>>(e1w, e1b, out);
}